// round 3
// baseline (speedup 1.0000x reference)
#include <cuda_runtime.h>
#include <cstdint>
#include <cstddef>

#define HWSZ 32768
#define WD   512
#define HD   64
#define BD   2
#define CH   128

// ---------------- scratch (no runtime allocation allowed) ----------------
__device__ float g_t[(size_t)BD * HWSZ * CH];   // relu(bn(fw@features)), layout [b][p][o]
__device__ float g_fa[CH], g_fsh[CH];           // feature-BN scale/shift
__device__ float g_A[CH * 3], g_pb2[CH];        // pos conv folded with pos-BN
__device__ float g_ews[3 * CH], g_esh[3];       // e2c conv folded with e-BN

// ---------------- setup: fold BN params ----------------
__global__ void setup_kernel(
    const float* __restrict__ pw,
    const float* __restrict__ pg, const float* __restrict__ pb,
    const float* __restrict__ pm, const float* __restrict__ pv,
    const float* __restrict__ fg, const float* __restrict__ fb,
    const float* __restrict__ fm, const float* __restrict__ fv,
    const float* __restrict__ ew,
    const float* __restrict__ eg, const float* __restrict__ eb,
    const float* __restrict__ em, const float* __restrict__ ev)
{
    int o = threadIdx.x;   // 128 threads
    __shared__ float ea_s[3];
    if (o < 3) {
        float ea = eg[o] * rsqrtf(ev[o] + 1e-5f);
        ea_s[o] = ea;
        g_esh[o] = eb[o] - em[o] * ea;
    }
    float fa = fg[o] * rsqrtf(fv[o] + 1e-5f);
    g_fa[o]  = fa;
    g_fsh[o] = fb[o] - fm[o] * fa;
    float pa = pg[o] * rsqrtf(pv[o] + 1e-5f);
    g_pb2[o] = pb[o] - pm[o] * pa;
    g_A[o * 3 + 0] = pa * pw[o * 3 + 0];
    g_A[o * 3 + 1] = pa * pw[o * 3 + 1];
    g_A[o * 3 + 2] = pa * pw[o * 3 + 2];
    __syncthreads();
    g_ews[0 * CH + o] = ea_s[0] * ew[0 * CH + o];
    g_ews[1 * CH + o] = ea_s[1] * ew[1 * CH + o];
    g_ews[2 * CH + o] = ea_s[2] * ew[2 * CH + o];
}

// ---------------- kernel 1: t = relu(bn(fw @ features)), per-pixel, f32x2 GEMV ----------------
// block: 128 threads (thread = output channel o), 64 pixels per block.
// Per thread: 32 packed f32x2 accumulators (pixel pairs).
__global__ void __launch_bounds__(128) gemm_kernel(
    const float* __restrict__ X,   // features [B][C][HW]
    const float* __restrict__ Wt)  // fw [128][128]
{
    __shared__ float s_w[32 * 129];  // w chunk, padded rows -> conflict-free
    __shared__ float s_x[32 * 64];   // x chunk

    const int o  = threadIdx.x;
    const int p0 = blockIdx.x * 64;
    const int b  = blockIdx.y;
    const float* xb = X + (size_t)b * CH * HWSZ + p0;

    double acc[32];
#pragma unroll
    for (int j = 0; j < 32; j++) acc[j] = 0.0;  // two packed fp32 zeros

    for (int c0 = 0; c0 < 128; c0 += 32) {
        __syncthreads();
        // stage w chunk transposed: s_w[cc*129+o2] = fw[o2][c0+cc]
#pragma unroll
        for (int k = 0; k < 32; k++) {
            int idx = o + k * 128;            // 4096 elems
            int o2 = idx >> 5, cc = idx & 31;
            s_w[cc * 129 + o2] = Wt[o2 * 128 + c0 + cc];
        }
        // stage x chunk: s_x[cc*64+i] = X[b][c0+cc][p0+i]
#pragma unroll
        for (int k = 0; k < 16; k++) {
            int idx = o + k * 128;            // 2048 elems
            int cc = idx >> 6, i = idx & 63;
            s_x[idx] = xb[(size_t)(c0 + cc) * HWSZ + i];
        }
        __syncthreads();

#pragma unroll
        for (int cc = 0; cc < 32; cc++) {
            float wv = s_w[cc * 129 + o];
            double w2;
            asm("mov.b64 %0, {%1,%1};" : "=d"(w2) : "f"(wv));
            const double2* xr = reinterpret_cast<const double2*>(&s_x[cc * 64]);
#pragma unroll
            for (int jj = 0; jj < 16; jj++) {
                double2 xv = xr[jj];  // 4 pixels
                asm("fma.rn.f32x2 %0, %1, %2, %0;" : "+d"(acc[2 * jj])     : "d"(xv.x), "d"(w2));
                asm("fma.rn.f32x2 %0, %1, %2, %0;" : "+d"(acc[2 * jj + 1]) : "d"(xv.y), "d"(w2));
            }
        }
    }

    const float fa = g_fa[o], fsh = g_fsh[o];
    float* tp = g_t + ((size_t)(b * HWSZ + p0)) * CH + o;
#pragma unroll
    for (int j = 0; j < 32; j++) {
        float lo, hi;
        asm("mov.b64 {%0,%1}, %2;" : "=f"(lo), "=f"(hi) : "d"(acc[j]));
        tp[(size_t)(2 * j) * CH]     = fmaxf(fmaf(fa, lo, fsh), 0.0f);
        tp[(size_t)(2 * j + 1) * CH] = fmaxf(fmaf(fa, hi, fsh), 0.0f);
    }
}

// ---------------- kernel 2: pos + neighbor max + e2c + cart_out ----------------
// block: 128 threads (thread = channel o), tile = 64 pixels of one image row.
__global__ void __launch_bounds__(128) fuse_kernel(
    const float* __restrict__ cart,
    const unsigned int* __restrict__ mask,  // 0 / nonzero (works for f32 or i32 storage)
    float* __restrict__ out)
{
    __shared__ float s_mu[9][64];
    __shared__ float s_r0[9][64], s_r1[9][64], s_r2[9][64];
    __shared__ float s_geo[64 * 129];  // stride 129 -> conflict-free both phases
    __shared__ float s_ews[3 * CH];

    const int tid = threadIdx.x;
    const int w0  = blockIdx.x * 64;
    const int h   = blockIdx.y;
    const int b   = blockIdx.z;
    const int cb  = b * 3 * HWSZ;

    // preload per-(pixel, neighbor) mask & relative coords
    for (int e = tid; e < 576; e += 128) {
        int pl = e / 9, n = e - pl * 9;
        int dh = n / 3 - 1, dw = n % 3 - 1;
        int wq = w0 + pl;
        int hn = h + dh, wn = wq + dw;
        float mu = 0.f, r0 = 0.f, r1 = 0.f, r2 = 0.f;
        if ((unsigned)hn < HD && (unsigned)wn < WD) {
            int pn = hn * WD + wn;
            if (mask[b * HWSZ + pn] != 0u) {
                mu = 1.f;
                int pc = h * WD + wq;
                r0 = cart[cb + pn]            - cart[cb + pc];
                r1 = cart[cb + HWSZ + pn]     - cart[cb + HWSZ + pc];
                r2 = cart[cb + 2 * HWSZ + pn] - cart[cb + 2 * HWSZ + pc];
            }
        }
        s_mu[n][pl] = mu; s_r0[n][pl] = r0; s_r1[n][pl] = r1; s_r2[n][pl] = r2;
    }
    for (int i = tid; i < 384; i += 128) s_ews[i] = g_ews[i];
    __syncthreads();

    // phase A: geo[o][pl] = max_n (t[o,pn] + relu(A.rel + b2)) * mu
    const int o = tid;
    const float A0 = g_A[o * 3], A1 = g_A[o * 3 + 1], A2 = g_A[o * 3 + 2], b2 = g_pb2[o];
    const int OFF[9] = {-WD - 1, -WD, -WD + 1, -1, 0, 1, WD - 1, WD, WD + 1};
    const int pg0 = b * HWSZ + h * WD + w0;
    for (int pl = 0; pl < 64; pl++) {
        float mx = 0.f;   // all candidates >= 0; masked/OOB neighbors contribute exactly 0
#pragma unroll
        for (int n = 0; n < 9; n++) {
            float mu = s_mu[n][pl];
            if (mu != 0.f) {
                float pos = fmaxf(fmaf(A0, s_r0[n][pl],
                                  fmaf(A1, s_r1[n][pl],
                                  fmaf(A2, s_r2[n][pl], b2))), 0.0f);
                float tv = g_t[(size_t)(pg0 + pl + OFF[n]) * CH + o];
                mx = fmaxf(mx, tv + pos);
            }
        }
        s_geo[pl * 129 + o] = mx;
    }
    __syncthreads();

    // phase B: e2c (3x128 reduction) + cart_out, one thread per pixel
    if (tid < 64) {
        int pl = tid;
        float s0 = 0.f, s1 = 0.f, s2 = 0.f;
#pragma unroll 4
        for (int oo = 0; oo < 128; oo++) {
            float gv = s_geo[pl * 129 + oo];
            s0 = fmaf(s_ews[oo],           gv, s0);
            s1 = fmaf(s_ews[128 + oo],     gv, s1);
            s2 = fmaf(s_ews[256 + oo],     gv, s2);
        }
        float mc = s_mu[4][pl];   // center mask
        int hw = h * WD + w0 + pl;
        const size_t OUTC = (size_t)BD * CH * HWSZ;
        out[OUTC + cb + hw]            = cart[cb + hw]            + (s0 + g_esh[0]) * mc;
        out[OUTC + cb + HWSZ + hw]     = cart[cb + HWSZ + hw]     + (s1 + g_esh[1]) * mc;
        out[OUTC + cb + 2 * HWSZ + hw] = cart[cb + 2 * HWSZ + hw] + (s2 + g_esh[2]) * mc;
    }
    // no barrier needed: phase C only READS s_geo (no writes after phase A's barrier)

    // phase C: write geo (channel-major output), coalesced 64-float segments
    const size_t gbase = (size_t)b * CH * HWSZ + (size_t)(h * WD + w0);
    for (int k = 0; k < 64; k++) {
        int idx = tid + k * 128;          // 8192 = 128 o x 64 pl
        int oo = idx >> 6, pl = idx & 63;
        out[gbase + (size_t)oo * HWSZ + pl] = s_geo[pl * 129 + oo];
    }
}

// ---------------- launch ----------------
extern "C" void kernel_launch(void* const* d_in, const int* in_sizes, int n_in,
                              void* d_out, int out_size)
{
    const float*        features = (const float*)d_in[0];
    const float*        cart     = (const float*)d_in[1];
    const unsigned int* mask     = (const unsigned int*)d_in[2];
    const float* pw = (const float*)d_in[3];
    const float* pg = (const float*)d_in[4];
    const float* pb = (const float*)d_in[5];
    const float* pm = (const float*)d_in[6];
    const float* pv = (const float*)d_in[7];
    const float* fw = (const float*)d_in[8];
    const float* fg = (const float*)d_in[9];
    const float* fb = (const float*)d_in[10];
    const float* fm = (const float*)d_in[11];
    const float* fv = (const float*)d_in[12];
    const float* ew = (const float*)d_in[13];
    const float* eg = (const float*)d_in[14];
    const float* eb = (const float*)d_in[15];
    const float* em = (const float*)d_in[16];
    const float* ev = (const float*)d_in[17];
    float* out = (float*)d_out;

    setup_kernel<<<1, 128>>>(pw, pg, pb, pm, pv, fg, fb, fm, fv, ew, eg, eb, em, ev);
    gemm_kernel<<<dim3(HWSZ / 64, BD), 128>>>(features, fw);
    fuse_kernel<<<dim3(WD / 64, HD, BD), 128>>>(cart, mask, out);
}

// round 4
// speedup vs baseline: 1.5755x; 1.5755x over previous
#include <cuda_runtime.h>
#include <cstdint>
#include <cstddef>

#define HWSZ 32768
#define WD   512
#define HD   64
#define BD   2
#define CH   128
#define EPSF 1e-5f

// ---------------- scratch (no runtime allocation allowed) ----------------
__device__ float g_t[(size_t)BD * HWSZ * CH];   // relu(bn(fw@features)), layout [b][p][o]

// ---------------- kernel 1: t = relu(bn(fw @ features)) ----------------
// 128 threads: thread t owns channels o_i = (t&31) + 32*i (i=0..3) and
// pixels px = (t>>5)*16 .. +15. Block covers 64 pixels. FFMA2 (fp32x2) mainloop.
__global__ void __launch_bounds__(128) gemm_kernel(
    const float* __restrict__ X,    // features [B][C][HW]
    const float* __restrict__ Wt,   // fw [128][128]
    const float* __restrict__ fg, const float* __restrict__ fb,
    const float* __restrict__ fm, const float* __restrict__ fv)
{
    __shared__ float2 s_wd[32 * 129];  // w chunk, [cc][o], value duplicated {w,w}
    __shared__ float  s_x[32 * 64];    // x chunk, [cc][px]

    const int t  = threadIdx.x;
    const int og = t & 31;
    const int wp = t >> 5;             // pixel group (0..3), 16 px each
    const int p0 = blockIdx.x * 64;
    const int b  = blockIdx.y;
    const float* xb = X + (size_t)b * CH * HWSZ + p0;

    double acc[4][8];
#pragma unroll
    for (int i = 0; i < 4; i++)
#pragma unroll
        for (int j = 0; j < 8; j++) acc[i][j] = 0.0;

    for (int c0 = 0; c0 < 128; c0 += 32) {
        __syncthreads();
        // stage w chunk transposed + duplicated: s_wd[cc*129+o] = {w[o][c0+cc], same}
#pragma unroll
        for (int k = 0; k < 32; k++) {
            int idx = t + k * 128;              // 4096 elems
            int cc = idx & 31, o2 = idx >> 5;   // consecutive lanes -> consecutive cc (coalesced read)
            float w = Wt[o2 * 128 + c0 + cc];
            s_wd[cc * 129 + o2] = make_float2(w, w);
        }
        // stage x chunk: s_x[cc*64+i] = X[b][c0+cc][p0+i]
#pragma unroll
        for (int k = 0; k < 16; k++) {
            int idx = t + k * 128;              // 2048 elems
            int cc = idx >> 6, i = idx & 63;
            s_x[idx] = xb[(size_t)(c0 + cc) * HWSZ + i];
        }
        __syncthreads();

#pragma unroll
        for (int cc = 0; cc < 32; cc++) {
            double w2[4];
#pragma unroll
            for (int i = 0; i < 4; i++)
                w2[i] = *reinterpret_cast<const double*>(&s_wd[cc * 129 + og + 32 * i]);
            const double2* xr = reinterpret_cast<const double2*>(&s_x[cc * 64 + wp * 16]);
#pragma unroll
            for (int j4 = 0; j4 < 4; j4++) {
                double2 xv = xr[j4];   // 4 pixels (two f32x2 pairs), broadcast within warp
#pragma unroll
                for (int i = 0; i < 4; i++) {
                    asm("fma.rn.f32x2 %0, %1, %2, %0;" : "+d"(acc[i][2 * j4])     : "d"(xv.x), "d"(w2[i]));
                    asm("fma.rn.f32x2 %0, %1, %2, %0;" : "+d"(acc[i][2 * j4 + 1]) : "d"(xv.y), "d"(w2[i]));
                }
            }
        }
    }

    // epilogue: fold BN (recomputed per thread, cheap) + relu, store p-major
    float fa[4], fsh[4];
#pragma unroll
    for (int i = 0; i < 4; i++) {
        int o = og + 32 * i;
        float a = fg[o] * rsqrtf(fv[o] + EPSF);
        fa[i] = a;
        fsh[i] = fb[o] - fm[o] * a;
    }
    float* tp = g_t + ((size_t)(b * HWSZ + p0 + wp * 16)) * CH + og;
#pragma unroll
    for (int j = 0; j < 8; j++) {
        float lo[4], hi[4];
#pragma unroll
        for (int i = 0; i < 4; i++)
            asm("mov.b64 {%0,%1}, %2;" : "=f"(lo[i]), "=f"(hi[i]) : "d"(acc[i][j]));
#pragma unroll
        for (int i = 0; i < 4; i++)
            tp[(size_t)(2 * j) * CH + 32 * i]     = fmaxf(fmaf(fa[i], lo[i], fsh[i]), 0.0f);
#pragma unroll
        for (int i = 0; i < 4; i++)
            tp[(size_t)(2 * j + 1) * CH + 32 * i] = fmaxf(fmaf(fa[i], hi[i], fsh[i]), 0.0f);
    }
}

// ---------------- kernel 2: pos + neighbor max + e2c + cart_out ----------------
// block: 128 threads (thread = channel o), tile = 64 pixels of one image row.
__global__ void __launch_bounds__(128) fuse_kernel(
    const float* __restrict__ cart,
    const unsigned int* __restrict__ mask,  // 0 / nonzero
    float* __restrict__ out,
    const float* __restrict__ pw,
    const float* __restrict__ pg, const float* __restrict__ pb,
    const float* __restrict__ pm, const float* __restrict__ pv,
    const float* __restrict__ ew,
    const float* __restrict__ eg, const float* __restrict__ eb,
    const float* __restrict__ em, const float* __restrict__ ev)
{
    __shared__ float s_mu[9][64];
    __shared__ float s_r0[9][64], s_r1[9][64], s_r2[9][64];
    __shared__ float s_geo[64 * 129];  // stride 129 -> conflict-free both phases
    __shared__ float s_ews[3 * CH];
    __shared__ float s_ea[3], s_esh[3];

    const int tid = threadIdx.x;
    const int w0  = blockIdx.x * 64;
    const int h   = blockIdx.y;
    const int b   = blockIdx.z;
    const int cb  = b * 3 * HWSZ;

    // per-(pixel, neighbor) mask & relative coords
    for (int e = tid; e < 576; e += 128) {
        int pl = e / 9, n = e - pl * 9;
        int dh = n / 3 - 1, dw = n % 3 - 1;
        int wq = w0 + pl;
        int hn = h + dh, wn = wq + dw;
        float mu = 0.f, r0 = 0.f, r1 = 0.f, r2 = 0.f;
        if ((unsigned)hn < HD && (unsigned)wn < WD) {
            int pn = hn * WD + wn;
            if (mask[b * HWSZ + pn] != 0u) {
                mu = 1.f;
                int pc = h * WD + wq;
                r0 = cart[cb + pn]            - cart[cb + pc];
                r1 = cart[cb + HWSZ + pn]     - cart[cb + HWSZ + pc];
                r2 = cart[cb + 2 * HWSZ + pn] - cart[cb + 2 * HWSZ + pc];
            }
        }
        s_mu[n][pl] = mu; s_r0[n][pl] = r0; s_r1[n][pl] = r1; s_r2[n][pl] = r2;
    }
    if (tid < 3) {
        float ea = eg[tid] * rsqrtf(ev[tid] + EPSF);
        s_ea[tid]  = ea;
        s_esh[tid] = eb[tid] - em[tid] * ea;
    }
    __syncthreads();

    // fold e2c weights (reads s_ea, written before barrier; used after next barrier)
    {
        s_ews[tid]       = s_ea[0] * ew[tid];
        s_ews[128 + tid] = s_ea[1] * ew[128 + tid];
        s_ews[256 + tid] = s_ea[2] * ew[256 + tid];
    }

    // phase A: geo[o][pl] = max_n (t[o,pn] + relu(A.rel + b2)) * mu ; 4-pixel unroll for MLP
    const int o = tid;
    const float pa = pg[o] * rsqrtf(pv[o] + EPSF);
    const float A0 = pa * pw[o * 3], A1 = pa * pw[o * 3 + 1], A2 = pa * pw[o * 3 + 2];
    const float b2 = pb[o] - pm[o] * pa;
    const int OFF[9] = {-WD - 1, -WD, -WD + 1, -1, 0, 1, WD - 1, WD, WD + 1};
    const float* tb = g_t + (size_t)(b * HWSZ + h * WD + w0) * CH + o;

    for (int pl0 = 0; pl0 < 64; pl0 += 4) {
        float mx[4] = {0.f, 0.f, 0.f, 0.f};  // candidates >= 0; masked/OOB contribute 0
#pragma unroll
        for (int n = 0; n < 9; n++) {
#pragma unroll
            for (int q = 0; q < 4; q++) {
                int pl = pl0 + q;
                float mu = s_mu[n][pl];
                if (mu != 0.f) {          // uniform across the warp (depends on pl,n only)
                    float pos = fmaxf(fmaf(A0, s_r0[n][pl],
                                      fmaf(A1, s_r1[n][pl],
                                      fmaf(A2, s_r2[n][pl], b2))), 0.0f);
                    float tv = tb[(long)(pl + OFF[n]) * CH];
                    mx[q] = fmaxf(mx[q], tv + pos);
                }
            }
        }
#pragma unroll
        for (int q = 0; q < 4; q++) s_geo[(pl0 + q) * 129 + o] = mx[q];
    }
    __syncthreads();

    // phase B: e2c (3x128 reduction) + cart_out, one thread per pixel
    if (tid < 64) {
        int pl = tid;
        float s0 = 0.f, s1 = 0.f, s2 = 0.f;
#pragma unroll 4
        for (int oo = 0; oo < 128; oo++) {
            float gv = s_geo[pl * 129 + oo];
            s0 = fmaf(s_ews[oo],       gv, s0);
            s1 = fmaf(s_ews[128 + oo], gv, s1);
            s2 = fmaf(s_ews[256 + oo], gv, s2);
        }
        float mc = s_mu[4][pl];   // center mask
        int hw = h * WD + w0 + pl;
        const size_t OUTC = (size_t)BD * CH * HWSZ;
        out[OUTC + cb + hw]            = cart[cb + hw]            + (s0 + s_esh[0]) * mc;
        out[OUTC + cb + HWSZ + hw]     = cart[cb + HWSZ + hw]     + (s1 + s_esh[1]) * mc;
        out[OUTC + cb + 2 * HWSZ + hw] = cart[cb + 2 * HWSZ + hw] + (s2 + s_esh[2]) * mc;
    }
    // phase C only reads s_geo (no writes since phase A's barrier) -> no extra barrier

    // phase C: write geo (channel-major output), coalesced 64-float segments
    const size_t gbase = (size_t)b * CH * HWSZ + (size_t)(h * WD + w0);
    for (int k = 0; k < 64; k++) {
        int idx = tid + k * 128;          // 8192 = 128 o x 64 pl
        int oo = idx >> 6, pl = idx & 63;
        out[gbase + (size_t)oo * HWSZ + pl] = s_geo[pl * 129 + oo];
    }
}

// ---------------- launch ----------------
extern "C" void kernel_launch(void* const* d_in, const int* in_sizes, int n_in,
                              void* d_out, int out_size)
{
    const float*        features = (const float*)d_in[0];
    const float*        cart     = (const float*)d_in[1];
    const unsigned int* mask     = (const unsigned int*)d_in[2];
    const float* pw = (const float*)d_in[3];
    const float* pg = (const float*)d_in[4];
    const float* pb = (const float*)d_in[5];
    const float* pm = (const float*)d_in[6];
    const float* pv = (const float*)d_in[7];
    const float* fw = (const float*)d_in[8];
    const float* fg = (const float*)d_in[9];
    const float* fb = (const float*)d_in[10];
    const float* fm = (const float*)d_in[11];
    const float* fv = (const float*)d_in[12];
    const float* ew = (const float*)d_in[13];
    const float* eg = (const float*)d_in[14];
    const float* eb = (const float*)d_in[15];
    const float* em = (const float*)d_in[16];
    const float* ev = (const float*)d_in[17];
    float* out = (float*)d_out;

    gemm_kernel<<<dim3(HWSZ / 64, BD), 128>>>(features, fw, fg, fb, fm, fv);
    fuse_kernel<<<dim3(WD / 64, HD, BD), 128>>>(cart, mask, out,
                                                pw, pg, pb, pm, pv,
                                                ew, eg, eb, em, ev);
}

// round 7
// speedup vs baseline: 2.0140x; 1.2783x over previous
#include <cuda_runtime.h>
#include <cstdint>
#include <cstddef>

#define HWSZ 32768
#define WD   512
#define HD   64
#define BD   2
#define CH   128
#define EPSF 1e-5f

// ---------------- scratch (no runtime allocation allowed) ----------------
__device__ float g_t[(size_t)BD * HWSZ * CH];   // relu(bn(fw@features)), layout [b][p][o]

// ---------------- kernel 1: t = relu(bn(fw @ features)) ----------------
// 128 threads: thread t owns channels o_i = (t&31) + 32*i (i=0..3) and
// pixels px = (t>>5)*16 .. +15. Block covers 64 pixels. FFMA2 (fp32x2) mainloop.
__global__ void __launch_bounds__(128) gemm_kernel(
    const float* __restrict__ X,    // features [B][C][HW]
    const float* __restrict__ Wt,   // fw [128][128]
    const float* __restrict__ fg, const float* __restrict__ fb,
    const float* __restrict__ fm, const float* __restrict__ fv)
{
    __shared__ float2 s_wd[32 * 129];  // w chunk, [cc][o], value duplicated {w,w}
    __shared__ float  s_x[32 * 64];    // x chunk, [cc][px]

    const int t  = threadIdx.x;
    const int og = t & 31;
    const int wp = t >> 5;             // pixel group (0..3), 16 px each
    const int p0 = blockIdx.x * 64;
    const int b  = blockIdx.y;
    const float* xb = X + (size_t)b * CH * HWSZ + p0;

    double acc[4][8];
#pragma unroll
    for (int i = 0; i < 4; i++)
#pragma unroll
        for (int j = 0; j < 8; j++) acc[i][j] = 0.0;

    for (int c0 = 0; c0 < 128; c0 += 32) {
        __syncthreads();
#pragma unroll
        for (int k = 0; k < 32; k++) {
            int idx = t + k * 128;
            int cc = idx & 31, o2 = idx >> 5;
            float w = Wt[o2 * 128 + c0 + cc];
            s_wd[cc * 129 + o2] = make_float2(w, w);
        }
#pragma unroll
        for (int k = 0; k < 16; k++) {
            int idx = t + k * 128;
            int cc = idx >> 6, i = idx & 63;
            s_x[idx] = xb[(size_t)(c0 + cc) * HWSZ + i];
        }
        __syncthreads();

#pragma unroll
        for (int cc = 0; cc < 32; cc++) {
            double w2[4];
#pragma unroll
            for (int i = 0; i < 4; i++)
                w2[i] = *reinterpret_cast<const double*>(&s_wd[cc * 129 + og + 32 * i]);
            const double2* xr = reinterpret_cast<const double2*>(&s_x[cc * 64 + wp * 16]);
#pragma unroll
            for (int j4 = 0; j4 < 4; j4++) {
                double2 xv = xr[j4];
#pragma unroll
                for (int i = 0; i < 4; i++) {
                    asm("fma.rn.f32x2 %0, %1, %2, %0;" : "+d"(acc[i][2 * j4])     : "d"(xv.x), "d"(w2[i]));
                    asm("fma.rn.f32x2 %0, %1, %2, %0;" : "+d"(acc[i][2 * j4 + 1]) : "d"(xv.y), "d"(w2[i]));
                }
            }
        }
    }

    float fa[4], fsh[4];
#pragma unroll
    for (int i = 0; i < 4; i++) {
        int o = og + 32 * i;
        float a = fg[o] * rsqrtf(fv[o] + EPSF);
        fa[i] = a;
        fsh[i] = fb[o] - fm[o] * a;
    }
    float* tp = g_t + ((size_t)(b * HWSZ + p0 + wp * 16)) * CH + og;
#pragma unroll
    for (int j = 0; j < 8; j++) {
        float lo[4], hi[4];
#pragma unroll
        for (int i = 0; i < 4; i++)
            asm("mov.b64 {%0,%1}, %2;" : "=f"(lo[i]), "=f"(hi[i]) : "d"(acc[i][j]));
#pragma unroll
        for (int i = 0; i < 4; i++)
            tp[(size_t)(2 * j) * CH + 32 * i]     = fmaxf(fmaf(fa[i], lo[i], fsh[i]), 0.0f);
#pragma unroll
        for (int i = 0; i < 4; i++)
            tp[(size_t)(2 * j + 1) * CH + 32 * i] = fmaxf(fmaf(fa[i], hi[i], fsh[i]), 0.0f);
    }
}

// ---------------- kernel 2: sliding-window pos + neighbor max + e2c + cart_out ----
// 128 threads = 4 warps. Warp w sweeps 16 pixels; lane l owns channels 4l..4l+3.
// Keeps a 3x3 window of t (float4) and v = A.c in registers; 3 LDG.128 per step.
__global__ void __launch_bounds__(128, 4) fuse_kernel(
    const float* __restrict__ cart,
    const unsigned int* __restrict__ mask,  // 0 / nonzero
    float* __restrict__ out,
    const float* __restrict__ pw,
    const float* __restrict__ pg, const float* __restrict__ pb,
    const float* __restrict__ pm, const float* __restrict__ pv,
    const float* __restrict__ ew,
    const float* __restrict__ eg, const float* __restrict__ eb,
    const float* __restrict__ em, const float* __restrict__ ev)
{
    __shared__ float s_mu[3][68];                 // mask window (0/1), col 0..65 = w0-1..w0+64
    __shared__ float s_c[3][3][68];               // cart window [coord][row][col]
    __shared__ __align__(16) float s_geo[64 * 132];
    __shared__ float s_ews[3 * CH];
    __shared__ float s_esh[3];

    const int tid = threadIdx.x;
    const int w0  = blockIdx.x * 64;
    const int h   = blockIdx.y;
    const int b   = blockIdx.z;
    const int cb  = b * 3 * HWSZ;

    // ---- preload 3x66 window of mask + cart ----
    for (int e = tid; e < 198; e += 128) {
        int r = e / 66, col = e - r * 66;
        int hh = h - 1 + r, ww = w0 - 1 + col;
        float mu = 0.f, c0 = 0.f, c1 = 0.f, c2 = 0.f;
        if ((unsigned)hh < HD && (unsigned)ww < WD) {
            int p = hh * WD + ww;
            mu = (mask[b * HWSZ + p] != 0u) ? 1.f : 0.f;
            c0 = cart[cb + p];
            c1 = cart[cb + HWSZ + p];
            c2 = cart[cb + 2 * HWSZ + p];
        }
        s_mu[r][col] = mu;
        s_c[0][r][col] = c0; s_c[1][r][col] = c1; s_c[2][r][col] = c2;
    }
    {   // fold e2c BN (each thread recomputes ea0..2: cheap, no extra barrier)
        float ea0 = eg[0] * rsqrtf(ev[0] + EPSF);
        float ea1 = eg[1] * rsqrtf(ev[1] + EPSF);
        float ea2 = eg[2] * rsqrtf(ev[2] + EPSF);
        s_ews[tid]       = ea0 * ew[tid];
        s_ews[128 + tid] = ea1 * ew[128 + tid];
        s_ews[256 + tid] = ea2 * ew[256 + tid];
        if (tid < 3) {
            float ea = eg[tid] * rsqrtf(ev[tid] + EPSF);
            s_esh[tid] = eb[tid] - em[tid] * ea;
        }
    }

    // ---- per-lane pos-conv params for 4 channels ----
    const int wa = tid >> 5;          // warp id: pixel strip
    const int l  = tid & 31;
    const int o0 = 4 * l;
    float A0[4], A1[4], A2[4], B2[4];
#pragma unroll
    for (int k = 0; k < 4; k++) {
        int o = o0 + k;
        float pa = pg[o] * rsqrtf(pv[o] + EPSF);
        A0[k] = pa * pw[o * 3];
        A1[k] = pa * pw[o * 3 + 1];
        A2[k] = pa * pw[o * 3 + 2];
        B2[k] = pb[o] - pm[o] * pa;
    }
    __syncthreads();

    // ---- phase A: sliding window sweep ----
    const int base = wa * 16;                       // leftmost window col of this strip
    int rowoff[3];
#pragma unroll
    for (int r = 0; r < 3; r++) {
        int hh = h - 1 + r;
        hh = hh < 0 ? 0 : (hh > HD - 1 ? HD - 1 : hh);
        rowoff[r] = hh * WD;
    }
    const float* tbase = g_t + (size_t)b * HWSZ * CH + o0;

    float tw[3][3][4];   // t window  [row][slot][ch]
    float vw[3][3][4];   // v = A.c   [row][slot][ch]

#pragma unroll
    for (int ci = 0; ci < 3; ci++) {                // initial fill: cols base..base+2
        int lc = base + ci;
        int colg = w0 - 1 + lc;
        colg = colg < 0 ? 0 : (colg > WD - 1 ? WD - 1 : colg);
#pragma unroll
        for (int r = 0; r < 3; r++) {
            float4 tv = *reinterpret_cast<const float4*>(tbase + (size_t)(rowoff[r] + colg) * CH);
            tw[r][ci][0] = tv.x; tw[r][ci][1] = tv.y; tw[r][ci][2] = tv.z; tw[r][ci][3] = tv.w;
            float c0 = s_c[0][r][lc], c1 = s_c[1][r][lc], c2 = s_c[2][r][lc];
#pragma unroll
            for (int k = 0; k < 4; k++)
                vw[r][ci][k] = fmaf(A0[k], c0, fmaf(A1[k], c1, A2[k] * c2));
        }
    }

#pragma unroll
    for (int j = 0; j < 16; j++) {
        // prefetch t of column base+j+3 (used next iteration)
        float tn[3][4];
        const int lcn = base + j + 3;
        if (j < 15) {
            int colg = w0 - 1 + lcn;                 // lcn >= 3 -> no low clamp needed
            colg = colg > WD - 1 ? WD - 1 : colg;
#pragma unroll
            for (int r = 0; r < 3; r++) {
                float4 tv = *reinterpret_cast<const float4*>(tbase + (size_t)(rowoff[r] + colg) * CH);
                tn[r][0] = tv.x; tn[r][1] = tv.y; tn[r][2] = tv.z; tn[r][3] = tv.w;
            }
        }

        // compute dest pixel pl = base + j; center v = vw[1][1]
        float wc[4], mx[4];
#pragma unroll
        for (int k = 0; k < 4; k++) { wc[k] = B2[k] - vw[1][1][k]; mx[k] = 0.f; }
#pragma unroll
        for (int r = 0; r < 3; r++)
#pragma unroll
            for (int ci = 0; ci < 3; ci++) {
                float mu = s_mu[r][base + j + ci];
#pragma unroll
                for (int k = 0; k < 4; k++) {
                    float pos = fmaxf(vw[r][ci][k] + wc[k], 0.0f);
                    mx[k] = fmaxf(mx[k], (tw[r][ci][k] + pos) * mu);
                }
            }
        *reinterpret_cast<float4*>(&s_geo[(base + j) * 132 + o0]) =
            make_float4(mx[0], mx[1], mx[2], mx[3]);

        // rotate window; slot 2 <- prefetched t and freshly computed v
        if (j < 15) {
#pragma unroll
            for (int r = 0; r < 3; r++) {
#pragma unroll
                for (int k = 0; k < 4; k++) {
                    tw[r][0][k] = tw[r][1][k]; tw[r][1][k] = tw[r][2][k]; tw[r][2][k] = tn[r][k];
                    vw[r][0][k] = vw[r][1][k]; vw[r][1][k] = vw[r][2][k];
                }
                float c0 = s_c[0][r][lcn], c1 = s_c[1][r][lcn], c2 = s_c[2][r][lcn];
#pragma unroll
                for (int k = 0; k < 4; k++)
                    vw[r][2][k] = fmaf(A0[k], c0, fmaf(A1[k], c1, A2[k] * c2));
            }
        }
    }
    __syncthreads();

    // ---- phase B: e2c (3x128) + cart_out, one thread per pixel ----
    if (tid < 64) {
        int pl = tid;
        float s0 = 0.f, s1 = 0.f, s2 = 0.f;
#pragma unroll 4
        for (int oo = 0; oo < 128; oo++) {
            float gv = s_geo[pl * 132 + oo];
            s0 = fmaf(s_ews[oo],       gv, s0);
            s1 = fmaf(s_ews[128 + oo], gv, s1);
            s2 = fmaf(s_ews[256 + oo], gv, s2);
        }
        float mc = s_mu[1][pl + 1];   // center mask
        int hw = h * WD + w0 + pl;
        const size_t OUTC = (size_t)BD * CH * HWSZ;
        out[OUTC + cb + hw]            = cart[cb + hw]            + (s0 + s_esh[0]) * mc;
        out[OUTC + cb + HWSZ + hw]     = cart[cb + HWSZ + hw]     + (s1 + s_esh[1]) * mc;
        out[OUTC + cb + 2 * HWSZ + hw] = cart[cb + 2 * HWSZ + hw] + (s2 + s_esh[2]) * mc;
    }
    // phase C only reads s_geo (no writes since the barrier) -> no extra barrier

    // ---- phase C: write geo (channel-major), coalesced ----
    const size_t gbase = (size_t)b * CH * HWSZ + (size_t)(h * WD + w0);
    for (int k = 0; k < 64; k++) {
        int idx = tid + k * 128;
        int oo = idx >> 6, pl = idx & 63;
        out[gbase + (size_t)oo * HWSZ + pl] = s_geo[pl * 132 + oo];
    }
}

// ---------------- launch ----------------
extern "C" void kernel_launch(void* const* d_in, const int* in_sizes, int n_in,
                              void* d_out, int out_size)
{
    const float*        features = (const float*)d_in[0];
    const float*        cart     = (const float*)d_in[1];
    const unsigned int* mask     = (const unsigned int*)d_in[2];
    const float* pw = (const float*)d_in[3];
    const float* pg = (const float*)d_in[4];
    const float* pb = (const float*)d_in[5];
    const float* pm = (const float*)d_in[6];
    const float* pv = (const float*)d_in[7];
    const float* fw = (const float*)d_in[8];
    const float* fg = (const float*)d_in[9];
    const float* fb = (const float*)d_in[10];
    const float* fm = (const float*)d_in[11];
    const float* fv = (const float*)d_in[12];
    const float* ew = (const float*)d_in[13];
    const float* eg = (const float*)d_in[14];
    const float* eb = (const float*)d_in[15];
    const float* em = (const float*)d_in[16];
    const float* ev = (const float*)d_in[17];
    float* out = (float*)d_out;

    gemm_kernel<<<dim3(HWSZ / 64, BD), 128>>>(features, fw, fg, fb, fm, fv);
    fuse_kernel<<<dim3(WD / 64, HD, BD), 128>>>(cart, mask, out,
                                                pw, pg, pb, pm, pv,
                                                ew, eg, eb, em, ev);
}

// round 10
// speedup vs baseline: 2.1454x; 1.0653x over previous
#include <cuda_runtime.h>
#include <cuda_bf16.h>
#include <cstdint>
#include <cstddef>

#define HWSZ 32768
#define WD   512
#define HD   64
#define BD   2
#define CH   128
#define EPSF 1e-5f

// ---------------- scratch (no runtime allocation allowed) ----------------
__device__ float          g_t[(size_t)BD * HWSZ * CH];     // relu(bn(fw@x)), [b*HW+p][o]
__device__ __nv_bfloat16  g_xb[(size_t)BD * HWSZ * 256];   // per pixel: [hi 128c | lo 128c]
__device__ __nv_bfloat16  g_wb[128 * 256];                 // per o-row:  [hi 128c | lo 128c]

__device__ __forceinline__ uint32_t smem_u32(const void* p) {
    uint32_t a;
    asm("{ .reg .u64 t; cvta.to.shared.u64 t, %1; cvt.u32.u64 %0, t; }" : "=r"(a) : "l"(p));
    return a;
}
__device__ __forceinline__ void ldm_x4(uint32_t& r0, uint32_t& r1, uint32_t& r2, uint32_t& r3,
                                       uint32_t addr) {
    asm volatile("ldmatrix.sync.aligned.m8n8.x4.shared.b16 {%0,%1,%2,%3}, [%4];"
        : "=r"(r0), "=r"(r1), "=r"(r2), "=r"(r3) : "r"(addr));
}
__device__ __forceinline__ void mma_bf16(float* d, uint32_t a0, uint32_t a1, uint32_t a2,
                                         uint32_t a3, uint32_t b0, uint32_t b1) {
    asm volatile("mma.sync.aligned.m16n8k16.row.col.f32.bf16.bf16.f32 "
        "{%0,%1,%2,%3}, {%4,%5,%6,%7}, {%8,%9}, {%0,%1,%2,%3};"
        : "+f"(d[0]), "+f"(d[1]), "+f"(d[2]), "+f"(d[3])
        : "r"(a0), "r"(a1), "r"(a2), "r"(a3), "r"(b0), "r"(b1));
}

// ---------------- convert: bf16 hi/lo split; X transposed to pixel-major ----------------
__global__ void __launch_bounds__(128) convert_kernel(
    const float* __restrict__ X, const float* __restrict__ Wt)
{
    const int t = threadIdx.x;
    if (blockIdx.x == BD * HWSZ / 64) {   // last block: W
#pragma unroll 4
        for (int k = 0; k < 128; k++) {
            int idx = t + 128 * k;
            int o = idx >> 7, c = idx & 127;
            float w = Wt[idx];
            __nv_bfloat16 hi = __float2bfloat16(w);
            __nv_bfloat16 lo = __float2bfloat16(w - __bfloat162float(hi));
            g_wb[o * 256 + c]       = hi;
            g_wb[o * 256 + 128 + c] = lo;
        }
        return;
    }
    __shared__ uint32_t s_hi[64][65], s_lo[64][65];   // [c-pair][pixel]
    const int gp0 = blockIdx.x * 64;
    const int b = gp0 >> 15, hw0 = gp0 & (HWSZ - 1);
    const float* xb = X + (size_t)b * CH * HWSZ + hw0;
#pragma unroll 4
    for (int k = 0; k < 32; k++) {
        int idx = t + 128 * k;            // 4096 = 64 cp x 64 p
        int cp = idx >> 6, p = idx & 63;
        float x0 = xb[(size_t)(2 * cp) * HWSZ + p];
        float x1 = xb[(size_t)(2 * cp + 1) * HWSZ + p];
        __nv_bfloat16 h0 = __float2bfloat16(x0), h1 = __float2bfloat16(x1);
        __nv_bfloat16 l0 = __float2bfloat16(x0 - __bfloat162float(h0));
        __nv_bfloat16 l1 = __float2bfloat16(x1 - __bfloat162float(h1));
        __nv_bfloat162 H = __halves2bfloat162(h0, h1);
        __nv_bfloat162 L = __halves2bfloat162(l0, l1);
        s_hi[cp][p] = *reinterpret_cast<uint32_t*>(&H);
        s_lo[cp][p] = *reinterpret_cast<uint32_t*>(&L);
    }
    __syncthreads();
    uint32_t* out32 = reinterpret_cast<uint32_t*>(g_xb) + (size_t)gp0 * 128;
#pragma unroll 4
    for (int k = 0; k < 64; k++) {
        int e = t + 128 * k;              // 8192 = 64 p x 128 u32
        int p = e >> 7, rem = e & 127;
        int sel = rem >> 6, cp = rem & 63;
        out32[(size_t)p * 128 + rem] = sel ? s_lo[cp][p] : s_hi[cp][p];
    }
}

// ---------------- HMMA GEMM: t = relu(bn(W @ X)) via mma.sync bf16, K=384 split ----------
// Block: 256 thr (8 warps), tile M=128 ch x N=128 px. Full W (128x256) + X tile (128x256)
// in smem, padded row stride 264 (rows land 4 banks apart -> ldmatrix conflict-free).
// Virtual K order: s=0..7 Whi*Xhi, 8..15 Whi*Xlo, 16..23 Wlo*Xhi.
#define SSTR 264
#define HMMA_SMEM (2 * 128 * SSTR * 2)

__global__ void __launch_bounds__(256) hmma_kernel(
    const float* __restrict__ fg, const float* __restrict__ fb,
    const float* __restrict__ fm, const float* __restrict__ fv)
{
    extern __shared__ __nv_bfloat16 smem[];
    __nv_bfloat16* sW = smem;
    __nv_bfloat16* sX = smem + 128 * SSTR;

    const int tid  = threadIdx.x;
    const int wid  = tid >> 5, lane = tid & 31;
    const int gp0  = blockIdx.x * 128;

    // ---- stage W + X tile (16B chunks, coalesced) ----
    {
        const uint4* srcW = reinterpret_cast<const uint4*>(g_wb);
        const uint4* srcX = reinterpret_cast<const uint4*>(g_xb) + (size_t)gp0 * 32;
        char* sWb = reinterpret_cast<char*>(sW);
        char* sXb = reinterpret_cast<char*>(sX);
#pragma unroll
        for (int k = 0; k < 16; k++) {
            int idx = tid + 256 * k;              // 4096 chunks each
            int row = idx >> 5, c16 = idx & 31;
            uint32_t off = (uint32_t)row * (SSTR * 2) + (uint32_t)c16 * 16;
            *reinterpret_cast<uint4*>(sWb + off) = srcW[idx];
            *reinterpret_cast<uint4*>(sXb + off) = srcX[idx];
        }
    }
    __syncthreads();

    // ---- warp tile: rows mrow0..+31, cols ncol0..+63 ----
    const int mrow0 = (wid & 3) * 32;
    const int ncol0 = (wid >> 2) * 64;
    const int r8 = lane & 7, tq = lane >> 3;

    // ldmatrix row base addresses (byte, within-row k offset added per step)
    const uint32_t sW0 = smem_u32(sW), sX0 = smem_u32(sX);
    uint32_t aBase[2], bBase[4];
#pragma unroll
    for (int mi = 0; mi < 2; mi++) {
        int row = mrow0 + mi * 16 + (tq & 1) * 8 + r8;
        aBase[mi] = sW0 + (uint32_t)row * (SSTR * 2) + (uint32_t)(tq >> 1) * 16;
    }
#pragma unroll
    for (int nj = 0; nj < 4; nj++) {
        int row = ncol0 + nj * 16 + (tq >> 1) * 8 + r8;
        bBase[nj] = sX0 + (uint32_t)row * (SSTR * 2) + (uint32_t)(tq & 1) * 16;
    }

    float d[2][8][4];
#pragma unroll
    for (int mi = 0; mi < 2; mi++)
#pragma unroll
        for (int nf = 0; nf < 8; nf++)
#pragma unroll
            for (int q = 0; q < 4; q++) d[mi][nf][q] = 0.f;

#pragma unroll
    for (int s = 0; s < 24; s++) {
        const int ak = (s < 16) ? ((s & 7) * 16) : (128 + (s & 7) * 16);
        const int bk = (s < 8) ? (s * 16) : ((s < 16) ? (128 + (s & 7) * 16) : ((s & 7) * 16));

        uint32_t a[2][4];
#pragma unroll
        for (int mi = 0; mi < 2; mi++)
            ldm_x4(a[mi][0], a[mi][1], a[mi][2], a[mi][3], aBase[mi] + (uint32_t)ak * 2);

        uint32_t bfr[8][2];
#pragma unroll
        for (int nj = 0; nj < 4; nj++) {
            uint32_t r0, r1, r2, r3;
            ldm_x4(r0, r1, r2, r3, bBase[nj] + (uint32_t)bk * 2);
            bfr[2 * nj][0] = r0; bfr[2 * nj][1] = r1;       // n: nj*16 .. +7
            bfr[2 * nj + 1][0] = r2; bfr[2 * nj + 1][1] = r3; // n: nj*16+8 .. +15
        }
#pragma unroll
        for (int mi = 0; mi < 2; mi++)
#pragma unroll
            for (int nf = 0; nf < 8; nf++)
                mma_bf16(d[mi][nf], a[mi][0], a[mi][1], a[mi][2], a[mi][3],
                         bfr[nf][0], bfr[nf][1]);
    }

    // ---- epilogue: BN + ReLU, store to g_t [p][o] ----
    // C frag: c0/c1 -> (m = lane>>2, n = (lane&3)*2 + {0,1}); c2/c3 -> m+8.
    float fa[2][2], fsh[2][2];
#pragma unroll
    for (int mi = 0; mi < 2; mi++)
#pragma unroll
        for (int hh = 0; hh < 2; hh++) {
            int m = mrow0 + mi * 16 + hh * 8 + (lane >> 2);
            float aa = fg[m] * rsqrtf(fv[m] + EPSF);
            fa[mi][hh] = aa;
            fsh[mi][hh] = fb[m] - fm[m] * aa;
        }
    float* tb = g_t + (size_t)gp0 * CH;
#pragma unroll
    for (int mi = 0; mi < 2; mi++) {
        int m0 = mrow0 + mi * 16 + (lane >> 2);
#pragma unroll
        for (int nf = 0; nf < 8; nf++) {
            int n0 = ncol0 + nf * 8 + (lane & 3) * 2;
            tb[(size_t)n0 * CH + m0]           = fmaxf(fmaf(fa[mi][0], d[mi][nf][0], fsh[mi][0]), 0.f);
            tb[(size_t)(n0 + 1) * CH + m0]     = fmaxf(fmaf(fa[mi][0], d[mi][nf][1], fsh[mi][0]), 0.f);
            tb[(size_t)n0 * CH + m0 + 8]       = fmaxf(fmaf(fa[mi][1], d[mi][nf][2], fsh[mi][1]), 0.f);
            tb[(size_t)(n0 + 1) * CH + m0 + 8] = fmaxf(fmaf(fa[mi][1], d[mi][nf][3], fsh[mi][1]), 0.f);
        }
    }
}

// ---------------- kernel 2: sliding-window pos + neighbor max + e2c + cart_out ----
__global__ void __launch_bounds__(128, 4) fuse_kernel(
    const float* __restrict__ cart,
    const unsigned int* __restrict__ mask,
    float* __restrict__ out,
    const float* __restrict__ pw,
    const float* __restrict__ pg, const float* __restrict__ pb,
    const float* __restrict__ pm, const float* __restrict__ pv,
    const float* __restrict__ ew,
    const float* __restrict__ eg, const float* __restrict__ eb,
    const float* __restrict__ em, const float* __restrict__ ev)
{
    __shared__ float s_mu[3][68];
    __shared__ float s_c[3][3][68];
    __shared__ __align__(16) float s_geo[64 * 132];
    __shared__ float s_ews[3 * CH];
    __shared__ float s_esh[3];

    const int tid = threadIdx.x;
    const int w0  = blockIdx.x * 64;
    const int h   = blockIdx.y;
    const int b   = blockIdx.z;
    const int cb  = b * 3 * HWSZ;

    for (int e = tid; e < 198; e += 128) {
        int r = e / 66, col = e - r * 66;
        int hh = h - 1 + r, ww = w0 - 1 + col;
        float mu = 0.f, c0 = 0.f, c1 = 0.f, c2 = 0.f;
        if ((unsigned)hh < HD && (unsigned)ww < WD) {
            int p = hh * WD + ww;
            mu = (mask[b * HWSZ + p] != 0u) ? 1.f : 0.f;
            c0 = cart[cb + p];
            c1 = cart[cb + HWSZ + p];
            c2 = cart[cb + 2 * HWSZ + p];
        }
        s_mu[r][col] = mu;
        s_c[0][r][col] = c0; s_c[1][r][col] = c1; s_c[2][r][col] = c2;
    }
    {
        float ea0 = eg[0] * rsqrtf(ev[0] + EPSF);
        float ea1 = eg[1] * rsqrtf(ev[1] + EPSF);
        float ea2 = eg[2] * rsqrtf(ev[2] + EPSF);
        s_ews[tid]       = ea0 * ew[tid];
        s_ews[128 + tid] = ea1 * ew[128 + tid];
        s_ews[256 + tid] = ea2 * ew[256 + tid];
        if (tid < 3) {
            float ea = eg[tid] * rsqrtf(ev[tid] + EPSF);
            s_esh[tid] = eb[tid] - em[tid] * ea;
        }
    }

    const int wa = tid >> 5;
    const int l  = tid & 31;
    const int o0 = 4 * l;
    float A0[4], A1[4], A2[4], B2[4];
#pragma unroll
    for (int k = 0; k < 4; k++) {
        int o = o0 + k;
        float pa = pg[o] * rsqrtf(pv[o] + EPSF);
        A0[k] = pa * pw[o * 3];
        A1[k] = pa * pw[o * 3 + 1];
        A2[k] = pa * pw[o * 3 + 2];
        B2[k] = pb[o] - pm[o] * pa;
    }
    __syncthreads();

    const int base = wa * 16;
    int rowoff[3];
#pragma unroll
    for (int r = 0; r < 3; r++) {
        int hh = h - 1 + r;
        hh = hh < 0 ? 0 : (hh > HD - 1 ? HD - 1 : hh);
        rowoff[r] = hh * WD;
    }
    const float* tbase = g_t + (size_t)b * HWSZ * CH + o0;

    float tw[3][3][4];
    float vw[3][3][4];

#pragma unroll
    for (int ci = 0; ci < 3; ci++) {
        int lc = base + ci;
        int colg = w0 - 1 + lc;
        colg = colg < 0 ? 0 : (colg > WD - 1 ? WD - 1 : colg);
#pragma unroll
        for (int r = 0; r < 3; r++) {
            float4 tv = *reinterpret_cast<const float4*>(tbase + (size_t)(rowoff[r] + colg) * CH);
            tw[r][ci][0] = tv.x; tw[r][ci][1] = tv.y; tw[r][ci][2] = tv.z; tw[r][ci][3] = tv.w;
            float c0 = s_c[0][r][lc], c1 = s_c[1][r][lc], c2 = s_c[2][r][lc];
#pragma unroll
            for (int k = 0; k < 4; k++)
                vw[r][ci][k] = fmaf(A0[k], c0, fmaf(A1[k], c1, A2[k] * c2));
        }
    }

#pragma unroll
    for (int j = 0; j < 16; j++) {
        float tn[3][4];
        const int lcn = base + j + 3;
        if (j < 15) {
            int colg = w0 - 1 + lcn;
            colg = colg > WD - 1 ? WD - 1 : colg;
#pragma unroll
            for (int r = 0; r < 3; r++) {
                float4 tv = *reinterpret_cast<const float4*>(tbase + (size_t)(rowoff[r] + colg) * CH);
                tn[r][0] = tv.x; tn[r][1] = tv.y; tn[r][2] = tv.z; tn[r][3] = tv.w;
            }
        }

        float wc[4], mx[4];
#pragma unroll
        for (int k = 0; k < 4; k++) { wc[k] = B2[k] - vw[1][1][k]; mx[k] = 0.f; }
#pragma unroll
        for (int r = 0; r < 3; r++)
#pragma unroll
            for (int ci = 0; ci < 3; ci++) {
                float mu = s_mu[r][base + j + ci];
#pragma unroll
                for (int k = 0; k < 4; k++) {
                    float pos = fmaxf(vw[r][ci][k] + wc[k], 0.0f);
                    mx[k] = fmaxf(mx[k], (tw[r][ci][k] + pos) * mu);
                }
            }
        *reinterpret_cast<float4*>(&s_geo[(base + j) * 132 + o0]) =
            make_float4(mx[0], mx[1], mx[2], mx[3]);

        if (j < 15) {
#pragma unroll
            for (int r = 0; r < 3; r++) {
#pragma unroll
                for (int k = 0; k < 4; k++) {
                    tw[r][0][k] = tw[r][1][k]; tw[r][1][k] = tw[r][2][k]; tw[r][2][k] = tn[r][k];
                    vw[r][0][k] = vw[r][1][k]; vw[r][1][k] = vw[r][2][k];
                }
                float c0 = s_c[0][r][lcn], c1 = s_c[1][r][lcn], c2 = s_c[2][r][lcn];
#pragma unroll
                for (int k = 0; k < 4; k++)
                    vw[r][2][k] = fmaf(A0[k], c0, fmaf(A1[k], c1, A2[k] * c2));
            }
        }
    }
    __syncthreads();

    if (tid < 64) {
        int pl = tid;
        float s0 = 0.f, s1 = 0.f, s2 = 0.f;
#pragma unroll 4
        for (int oo = 0; oo < 128; oo++) {
            float gv = s_geo[pl * 132 + oo];
            s0 = fmaf(s_ews[oo],       gv, s0);
            s1 = fmaf(s_ews[128 + oo], gv, s1);
            s2 = fmaf(s_ews[256 + oo], gv, s2);
        }
        float mc = s_mu[1][pl + 1];
        int hw = h * WD + w0 + pl;
        const size_t OUTC = (size_t)BD * CH * HWSZ;
        out[OUTC + cb + hw]            = cart[cb + hw]            + (s0 + s_esh[0]) * mc;
        out[OUTC + cb + HWSZ + hw]     = cart[cb + HWSZ + hw]     + (s1 + s_esh[1]) * mc;
        out[OUTC + cb + 2 * HWSZ + hw] = cart[cb + 2 * HWSZ + hw] + (s2 + s_esh[2]) * mc;
    }

    const size_t gbase = (size_t)b * CH * HWSZ + (size_t)(h * WD + w0);
    for (int k = 0; k < 64; k++) {
        int idx = tid + k * 128;
        int oo = idx >> 6, pl = idx & 63;
        out[gbase + (size_t)oo * HWSZ + pl] = s_geo[pl * 132 + oo];
    }
}

// ---------------- launch ----------------
extern "C" void kernel_launch(void* const* d_in, const int* in_sizes, int n_in,
                              void* d_out, int out_size)
{
    const float*        features = (const float*)d_in[0];
    const float*        cart     = (const float*)d_in[1];
    const unsigned int* mask     = (const unsigned int*)d_in[2];
    const float* pw = (const float*)d_in[3];
    const float* pg = (const float*)d_in[4];
    const float* pb = (const float*)d_in[5];
    const float* pm = (const float*)d_in[6];
    const float* pv = (const float*)d_in[7];
    const float* fw = (const float*)d_in[8];
    const float* fg = (const float*)d_in[9];
    const float* fb = (const float*)d_in[10];
    const float* fm = (const float*)d_in[11];
    const float* fv = (const float*)d_in[12];
    const float* ew = (const float*)d_in[13];
    const float* eg = (const float*)d_in[14];
    const float* eb = (const float*)d_in[15];
    const float* em = (const float*)d_in[16];
    const float* ev = (const float*)d_in[17];
    float* out = (float*)d_out;

    cudaFuncSetAttribute(hmma_kernel, cudaFuncAttributeMaxDynamicSharedMemorySize, HMMA_SMEM);

    convert_kernel<<<BD * HWSZ / 64 + 1, 128>>>(features, fw);
    hmma_kernel<<<BD * HWSZ / 128, 256, HMMA_SMEM>>>(fg, fb, fm, fv);
    fuse_kernel<<<dim3(WD / 64, HD, BD), 128>>>(cart, mask, out,
                                                pw, pg, pb, pm, pv,
                                                ew, eg, eb, em, ev);
}

// round 14
// speedup vs baseline: 2.7918x; 1.3013x over previous
#include <cuda_runtime.h>
#include <cuda_bf16.h>
#include <cstdint>
#include <cstddef>

#define HWSZ 32768
#define WD   512
#define HD   64
#define BD   2
#define CH   128
#define EPSF 1e-5f

// ---------------- scratch (no runtime allocation allowed) ----------------
__device__ float g_t[(size_t)BD * HWSZ * CH];   // relu(bn(fw@x)), [b*HW+p][o]

__device__ __forceinline__ uint32_t smem_u32(const void* p) {
    uint32_t a;
    asm("{ .reg .u64 t; cvta.to.shared.u64 t, %1; cvt.u32.u64 %0, t; }" : "=r"(a) : "l"(p));
    return a;
}
__device__ __forceinline__ void ldm_x4(uint32_t& r0, uint32_t& r1, uint32_t& r2, uint32_t& r3,
                                       uint32_t addr) {
    asm volatile("ldmatrix.sync.aligned.m8n8.x4.shared.b16 {%0,%1,%2,%3}, [%4];"
        : "=r"(r0), "=r"(r1), "=r"(r2), "=r"(r3) : "r"(addr));
}
__device__ __forceinline__ void mma_bf16(float* d, uint32_t a0, uint32_t a1, uint32_t a2,
                                         uint32_t a3, uint32_t b0, uint32_t b1) {
    asm volatile("mma.sync.aligned.m16n8k16.row.col.f32.bf16.bf16.f32 "
        "{%0,%1,%2,%3}, {%4,%5,%6,%7}, {%8,%9}, {%0,%1,%2,%3};"
        : "+f"(d[0]), "+f"(d[1]), "+f"(d[2]), "+f"(d[3])
        : "r"(a0), "r"(a1), "r"(a2), "r"(a3), "r"(b0), "r"(b1));
}
__device__ __forceinline__ void split2(float x0, float x1, uint32_t& H, uint32_t& L) {
    __nv_bfloat16 h0 = __float2bfloat16(x0), h1 = __float2bfloat16(x1);
    __nv_bfloat16 l0 = __float2bfloat16(x0 - __bfloat162float(h0));
    __nv_bfloat16 l1 = __float2bfloat16(x1 - __bfloat162float(h1));
    __nv_bfloat162 Hh = __halves2bfloat162(h0, h1);
    __nv_bfloat162 Ll = __halves2bfloat162(l0, l1);
    H = *reinterpret_cast<uint32_t*>(&Hh);
    L = *reinterpret_cast<uint32_t*>(&Ll);
}

// ---------------- fused HMMA GEMM: t = relu(bn(W @ X)), K=384 bf16 split ----------
// Block: 256 thr (8 warps), tile M=128 ch x N=128 px.
// smem: sW bf16[128][264] (hi|lo k-major), sX bf16[128][264] (pixel rows), sF f32[128][132].
// Staging converts fp32->bf16 hi/lo in-block (no global round trip).
#define SSTR 264
#define XPAD 132
#define HMMA_SMEM (2 * 128 * SSTR * 2 + 128 * XPAD * 4)

__global__ void __launch_bounds__(256) hmma_kernel(
    const float* __restrict__ X,  const float* __restrict__ Wt,
    const float* __restrict__ fg, const float* __restrict__ fb,
    const float* __restrict__ fm, const float* __restrict__ fv)
{
    extern __shared__ __nv_bfloat16 smem[];
    __nv_bfloat16* sW = smem;
    __nv_bfloat16* sX = smem + 128 * SSTR;
    float*         sF = reinterpret_cast<float*>(smem + 2 * 128 * SSTR);

    const int tid  = threadIdx.x;
    const int wid  = tid >> 5, lane = tid & 31;
    const int gp0  = blockIdx.x * 128;
    const int b    = gp0 >> 15, hw0 = gp0 & (HWSZ - 1);

    // ---- stage 1: X fp32 tile (row=channel) + W convert (row=o, k-major hi|lo) ----
    {
        const float* xb = X + (size_t)b * CH * HWSZ + hw0;
        char* sFb = reinterpret_cast<char*>(sF);
#pragma unroll
        for (int k = 0; k < 16; k++) {
            int idx = tid + 256 * k;              // 4096 float4
            int row = idx >> 5, f4 = idx & 31;
            float4 v = *reinterpret_cast<const float4*>(xb + (size_t)row * HWSZ + 4 * f4);
            *reinterpret_cast<float4*>(sFb + (uint32_t)row * (XPAD * 4) + 16u * f4) = v;
        }
        char* sWb = reinterpret_cast<char*>(sW);
#pragma unroll
        for (int k = 0; k < 32; k++) {
            int idx = tid + 256 * k;              // 8192 float pairs
            int row = idx >> 6, cp = idx & 63;
            float2 w2 = *reinterpret_cast<const float2*>(Wt + row * 128 + 2 * cp);
            uint32_t H, L;
            split2(w2.x, w2.y, H, L);
            *reinterpret_cast<uint32_t*>(sWb + (uint32_t)row * (SSTR * 2) + 4u * cp)        = H;
            *reinterpret_cast<uint32_t*>(sWb + (uint32_t)row * (SSTR * 2) + 256u + 4u * cp) = L;
        }
    }
    __syncthreads();

    // ---- stage 2: transposed convert X -> sX (row=pixel, [hi 128 | lo 128]) ----
    {
        const int p = tid & 127, half = tid >> 7;
        char* sXb = reinterpret_cast<char*>(sX);
#pragma unroll
        for (int j = 0; j < 8; j++) {
            const int c0 = half * 64 + j * 8;
            float v[8];
#pragma unroll
            for (int i = 0; i < 8; i++) v[i] = sF[(c0 + i) * XPAD + p];   // lanes vary p: conflict-free
            uint32_t H[4], L[4];
#pragma unroll
            for (int i = 0; i < 4; i++) split2(v[2 * i], v[2 * i + 1], H[i], L[i]);
            uint4 hv = make_uint4(H[0], H[1], H[2], H[3]);
            uint4 lv = make_uint4(L[0], L[1], L[2], L[3]);
            // STS.128, lane stride 528B: quarter-wavefront start banks 4p%32 partition 32 banks
            *reinterpret_cast<uint4*>(sXb + (uint32_t)p * (SSTR * 2) + (uint32_t)c0 * 2u)        = hv;
            *reinterpret_cast<uint4*>(sXb + (uint32_t)p * (SSTR * 2) + 256u + (uint32_t)c0 * 2u) = lv;
        }
    }
    __syncthreads();

    // ---- warp tile: rows mrow0..+31, cols ncol0..+63 ----
    const int mrow0 = (wid & 3) * 32;
    const int ncol0 = (wid >> 2) * 64;
    const int r8 = lane & 7, tq = lane >> 3;

    const uint32_t sW0 = smem_u32(sW), sX0 = smem_u32(sX);
    uint32_t aBase[2], bBase[4];
#pragma unroll
    for (int mi = 0; mi < 2; mi++) {
        int row = mrow0 + mi * 16 + (tq & 1) * 8 + r8;
        aBase[mi] = sW0 + (uint32_t)row * (SSTR * 2) + (uint32_t)(tq >> 1) * 16;
    }
#pragma unroll
    for (int nj = 0; nj < 4; nj++) {
        int row = ncol0 + nj * 16 + (tq >> 1) * 8 + r8;
        bBase[nj] = sX0 + (uint32_t)row * (SSTR * 2) + (uint32_t)(tq & 1) * 16;
    }

    float d[2][8][4];
#pragma unroll
    for (int mi = 0; mi < 2; mi++)
#pragma unroll
        for (int nf = 0; nf < 8; nf++)
#pragma unroll
            for (int q = 0; q < 4; q++) d[mi][nf][q] = 0.f;

    // virtual K: s=0..7 Whi*Xhi, 8..15 Whi*Xlo, 16..23 Wlo*Xhi
#pragma unroll
    for (int s = 0; s < 24; s++) {
        const int ak = (s < 16) ? ((s & 7) * 16) : (128 + (s & 7) * 16);
        const int bk = (s < 8) ? (s * 16) : ((s < 16) ? (128 + (s & 7) * 16) : ((s & 7) * 16));

        uint32_t a[2][4];
#pragma unroll
        for (int mi = 0; mi < 2; mi++)
            ldm_x4(a[mi][0], a[mi][1], a[mi][2], a[mi][3], aBase[mi] + (uint32_t)ak * 2);

        uint32_t bfr[8][2];
#pragma unroll
        for (int nj = 0; nj < 4; nj++) {
            uint32_t r0, r1, r2, r3;
            ldm_x4(r0, r1, r2, r3, bBase[nj] + (uint32_t)bk * 2);
            bfr[2 * nj][0] = r0; bfr[2 * nj][1] = r1;
            bfr[2 * nj + 1][0] = r2; bfr[2 * nj + 1][1] = r3;
        }
#pragma unroll
        for (int mi = 0; mi < 2; mi++)
#pragma unroll
            for (int nf = 0; nf < 8; nf++)
                mma_bf16(d[mi][nf], a[mi][0], a[mi][1], a[mi][2], a[mi][3],
                         bfr[nf][0], bfr[nf][1]);
    }

    // ---- epilogue: BN + ReLU, store to g_t [p][o] ----
    float fa[2][2], fsh[2][2];
#pragma unroll
    for (int mi = 0; mi < 2; mi++)
#pragma unroll
        for (int hh = 0; hh < 2; hh++) {
            int m = mrow0 + mi * 16 + hh * 8 + (lane >> 2);
            float aa = fg[m] * rsqrtf(fv[m] + EPSF);
            fa[mi][hh] = aa;
            fsh[mi][hh] = fb[m] - fm[m] * aa;
        }
    float* tb = g_t + (size_t)gp0 * CH;
#pragma unroll
    for (int mi = 0; mi < 2; mi++) {
        int m0 = mrow0 + mi * 16 + (lane >> 2);
#pragma unroll
        for (int nf = 0; nf < 8; nf++) {
            int n0 = ncol0 + nf * 8 + (lane & 3) * 2;
            tb[(size_t)n0 * CH + m0]           = fmaxf(fmaf(fa[mi][0], d[mi][nf][0], fsh[mi][0]), 0.f);
            tb[(size_t)(n0 + 1) * CH + m0]     = fmaxf(fmaf(fa[mi][0], d[mi][nf][1], fsh[mi][0]), 0.f);
            tb[(size_t)n0 * CH + m0 + 8]       = fmaxf(fmaf(fa[mi][1], d[mi][nf][2], fsh[mi][1]), 0.f);
            tb[(size_t)(n0 + 1) * CH + m0 + 8] = fmaxf(fmaf(fa[mi][1], d[mi][nf][3], fsh[mi][1]), 0.f);
        }
    }
}

// ---------------- kernel 2: sliding-window pos + neighbor max + e2c + cart_out ----
__global__ void __launch_bounds__(128, 4) fuse_kernel(
    const float* __restrict__ cart,
    const unsigned int* __restrict__ mask,
    float* __restrict__ out,
    const float* __restrict__ pw,
    const float* __restrict__ pg, const float* __restrict__ pb,
    const float* __restrict__ pm, const float* __restrict__ pv,
    const float* __restrict__ ew,
    const float* __restrict__ eg, const float* __restrict__ eb,
    const float* __restrict__ em, const float* __restrict__ ev)
{
    __shared__ float s_mu[3][68];
    __shared__ float s_c[3][3][68];
    __shared__ __align__(16) float s_geo[64 * 132];
    __shared__ float s_ews[3 * CH];
    __shared__ float s_esh[3];

    const int tid = threadIdx.x;
    const int w0  = blockIdx.x * 64;
    const int h   = blockIdx.y;
    const int b   = blockIdx.z;
    const int cb  = b * 3 * HWSZ;

    for (int e = tid; e < 198; e += 128) {
        int r = e / 66, col = e - r * 66;
        int hh = h - 1 + r, ww = w0 - 1 + col;
        float mu = 0.f, c0 = 0.f, c1 = 0.f, c2 = 0.f;
        if ((unsigned)hh < HD && (unsigned)ww < WD) {
            int p = hh * WD + ww;
            mu = (mask[b * HWSZ + p] != 0u) ? 1.f : 0.f;
            c0 = cart[cb + p];
            c1 = cart[cb + HWSZ + p];
            c2 = cart[cb + 2 * HWSZ + p];
        }
        s_mu[r][col] = mu;
        s_c[0][r][col] = c0; s_c[1][r][col] = c1; s_c[2][r][col] = c2;
    }
    {
        float ea0 = eg[0] * rsqrtf(ev[0] + EPSF);
        float ea1 = eg[1] * rsqrtf(ev[1] + EPSF);
        float ea2 = eg[2] * rsqrtf(ev[2] + EPSF);
        s_ews[tid]       = ea0 * ew[tid];
        s_ews[128 + tid] = ea1 * ew[128 + tid];
        s_ews[256 + tid] = ea2 * ew[256 + tid];
        if (tid < 3) {
            float ea = eg[tid] * rsqrtf(ev[tid] + EPSF);
            s_esh[tid] = eb[tid] - em[tid] * ea;
        }
    }

    const int wa = tid >> 5;
    const int l  = tid & 31;
    const int o0 = 4 * l;
    float A0[4], A1[4], A2[4], B2[4];
#pragma unroll
    for (int k = 0; k < 4; k++) {
        int o = o0 + k;
        float pa = pg[o] * rsqrtf(pv[o] + EPSF);
        A0[k] = pa * pw[o * 3];
        A1[k] = pa * pw[o * 3 + 1];
        A2[k] = pa * pw[o * 3 + 2];
        B2[k] = pb[o] - pm[o] * pa;
    }
    __syncthreads();

    const int base = wa * 16;
    int rowoff[3];
#pragma unroll
    for (int r = 0; r < 3; r++) {
        int hh = h - 1 + r;
        hh = hh < 0 ? 0 : (hh > HD - 1 ? HD - 1 : hh);
        rowoff[r] = hh * WD;
    }
    const float* tbase = g_t + (size_t)b * HWSZ * CH + o0;

    float tw[3][3][4];
    float vw[3][3][4];

#pragma unroll
    for (int ci = 0; ci < 3; ci++) {
        int lc = base + ci;
        int colg = w0 - 1 + lc;
        colg = colg < 0 ? 0 : (colg > WD - 1 ? WD - 1 : colg);
#pragma unroll
        for (int r = 0; r < 3; r++) {
            float4 tv = *reinterpret_cast<const float4*>(tbase + (size_t)(rowoff[r] + colg) * CH);
            tw[r][ci][0] = tv.x; tw[r][ci][1] = tv.y; tw[r][ci][2] = tv.z; tw[r][ci][3] = tv.w;
            float c0 = s_c[0][r][lc], c1 = s_c[1][r][lc], c2 = s_c[2][r][lc];
#pragma unroll
            for (int k = 0; k < 4; k++)
                vw[r][ci][k] = fmaf(A0[k], c0, fmaf(A1[k], c1, A2[k] * c2));
        }
    }

#pragma unroll
    for (int j = 0; j < 16; j++) {
        float tn[3][4];
        const int lcn = base + j + 3;
        if (j < 15) {
            int colg = w0 - 1 + lcn;
            colg = colg > WD - 1 ? WD - 1 : colg;
#pragma unroll
            for (int r = 0; r < 3; r++) {
                float4 tv = *reinterpret_cast<const float4*>(tbase + (size_t)(rowoff[r] + colg) * CH);
                tn[r][0] = tv.x; tn[r][1] = tv.y; tn[r][2] = tv.z; tn[r][3] = tv.w;
            }
        }

        float wc[4], mx[4];
#pragma unroll
        for (int k = 0; k < 4; k++) { wc[k] = B2[k] - vw[1][1][k]; mx[k] = 0.f; }
#pragma unroll
        for (int r = 0; r < 3; r++)
#pragma unroll
            for (int ci = 0; ci < 3; ci++) {
                float mu = s_mu[r][base + j + ci];
#pragma unroll
                for (int k = 0; k < 4; k++) {
                    float pos = fmaxf(vw[r][ci][k] + wc[k], 0.0f);
                    mx[k] = fmaxf(mx[k], (tw[r][ci][k] + pos) * mu);
                }
            }
        *reinterpret_cast<float4*>(&s_geo[(base + j) * 132 + o0]) =
            make_float4(mx[0], mx[1], mx[2], mx[3]);

        if (j < 15) {
#pragma unroll
            for (int r = 0; r < 3; r++) {
#pragma unroll
                for (int k = 0; k < 4; k++) {
                    tw[r][0][k] = tw[r][1][k]; tw[r][1][k] = tw[r][2][k]; tw[r][2][k] = tn[r][k];
                    vw[r][0][k] = vw[r][1][k]; vw[r][1][k] = vw[r][2][k];
                }
                float c0 = s_c[0][r][lcn], c1 = s_c[1][r][lcn], c2 = s_c[2][r][lcn];
#pragma unroll
                for (int k = 0; k < 4; k++)
                    vw[r][2][k] = fmaf(A0[k], c0, fmaf(A1[k], c1, A2[k] * c2));
            }
        }
    }
    __syncthreads();

    if (tid < 64) {
        int pl = tid;
        float s0 = 0.f, s1 = 0.f, s2 = 0.f;
#pragma unroll 4
        for (int oo = 0; oo < 128; oo++) {
            float gv = s_geo[pl * 132 + oo];
            s0 = fmaf(s_ews[oo],       gv, s0);
            s1 = fmaf(s_ews[128 + oo], gv, s1);
            s2 = fmaf(s_ews[256 + oo], gv, s2);
        }
        float mc = s_mu[1][pl + 1];
        int hw = h * WD + w0 + pl;
        const size_t OUTC = (size_t)BD * CH * HWSZ;
        out[OUTC + cb + hw]            = cart[cb + hw]            + (s0 + s_esh[0]) * mc;
        out[OUTC + cb + HWSZ + hw]     = cart[cb + HWSZ + hw]     + (s1 + s_esh[1]) * mc;
        out[OUTC + cb + 2 * HWSZ + hw] = cart[cb + 2 * HWSZ + hw] + (s2 + s_esh[2]) * mc;
    }

    const size_t gbase = (size_t)b * CH * HWSZ + (size_t)(h * WD + w0);
    for (int k = 0; k < 64; k++) {
        int idx = tid + k * 128;
        int oo = idx >> 6, pl = idx & 63;
        out[gbase + (size_t)oo * HWSZ + pl] = s_geo[pl * 132 + oo];
    }
}

// ---------------- launch ----------------
extern "C" void kernel_launch(void* const* d_in, const int* in_sizes, int n_in,
                              void* d_out, int out_size)
{
    const float*        features = (const float*)d_in[0];
    const float*        cart     = (const float*)d_in[1];
    const unsigned int* mask     = (const unsigned int*)d_in[2];
    const float* pw = (const float*)d_in[3];
    const float* pg = (const float*)d_in[4];
    const float* pb = (const float*)d_in[5];
    const float* pm = (const float*)d_in[6];
    const float* pv = (const float*)d_in[7];
    const float* fw = (const float*)d_in[8];
    const float* fg = (const float*)d_in[9];
    const float* fb = (const float*)d_in[10];
    const float* fm = (const float*)d_in[11];
    const float* fv = (const float*)d_in[12];
    const float* ew = (const float*)d_in[13];
    const float* eg = (const float*)d_in[14];
    const float* eb = (const float*)d_in[15];
    const float* em = (const float*)d_in[16];
    const float* ev = (const float*)d_in[17];
    float* out = (float*)d_out;

    cudaFuncSetAttribute(hmma_kernel, cudaFuncAttributeMaxDynamicSharedMemorySize, HMMA_SMEM);

    hmma_kernel<<<BD * HWSZ / 128, 256, HMMA_SMEM>>>(features, fw, fg, fb, fm, fv);
    fuse_kernel<<<dim3(WD / 64, HD, BD), 128>>>(cart, mask, out,
                                                pw, pg, pb, pm, pv,
                                                ew, eg, eb, em, ev);
}

// round 15
// speedup vs baseline: 3.0196x; 1.0816x over previous
#include <cuda_runtime.h>
#include <cuda_bf16.h>
#include <cstdint>
#include <cstddef>

#define HWSZ 32768
#define WD   512
#define HD   64
#define BD   2
#define CH   128
#define EPSF 1e-5f

// ---------------- scratch (no runtime allocation allowed) ----------------
__device__ float         g_t[(size_t)BD * HWSZ * CH];   // relu(bn(fw@x)), [b*HW+p][o]
__device__ __nv_bfloat16 g_wb[128 * 256];               // W split: per o-row [hi 128 | lo 128]

__device__ __forceinline__ uint32_t smem_u32(const void* p) {
    uint32_t a;
    asm("{ .reg .u64 t; cvta.to.shared.u64 t, %1; cvt.u32.u64 %0, t; }" : "=r"(a) : "l"(p));
    return a;
}
__device__ __forceinline__ void ldm_x4(uint32_t& r0, uint32_t& r1, uint32_t& r2, uint32_t& r3,
                                       uint32_t addr) {
    asm volatile("ldmatrix.sync.aligned.m8n8.x4.shared.b16 {%0,%1,%2,%3}, [%4];"
        : "=r"(r0), "=r"(r1), "=r"(r2), "=r"(r3) : "r"(addr));
}
__device__ __forceinline__ void ldm_x4_t(uint32_t& r0, uint32_t& r1, uint32_t& r2, uint32_t& r3,
                                         uint32_t addr) {
    asm volatile("ldmatrix.sync.aligned.m8n8.x4.trans.shared.b16 {%0,%1,%2,%3}, [%4];"
        : "=r"(r0), "=r"(r1), "=r"(r2), "=r"(r3) : "r"(addr));
}
__device__ __forceinline__ void mma_bf16(float* d, uint32_t a0, uint32_t a1, uint32_t a2,
                                         uint32_t a3, uint32_t b0, uint32_t b1) {
    asm volatile("mma.sync.aligned.m16n8k16.row.col.f32.bf16.bf16.f32 "
        "{%0,%1,%2,%3}, {%4,%5,%6,%7}, {%8,%9}, {%0,%1,%2,%3};"
        : "+f"(d[0]), "+f"(d[1]), "+f"(d[2]), "+f"(d[3])
        : "r"(a0), "r"(a1), "r"(a2), "r"(a3), "r"(b0), "r"(b1));
}
__device__ __forceinline__ void split2(float x0, float x1, uint32_t& H, uint32_t& L) {
    __nv_bfloat16 h0 = __float2bfloat16(x0), h1 = __float2bfloat16(x1);
    __nv_bfloat16 l0 = __float2bfloat16(x0 - __bfloat162float(h0));
    __nv_bfloat16 l1 = __float2bfloat16(x1 - __bfloat162float(h1));
    __nv_bfloat162 Hh = __halves2bfloat162(h0, h1);
    __nv_bfloat162 Ll = __halves2bfloat162(l0, l1);
    H = *reinterpret_cast<uint32_t*>(&Hh);
    L = *reinterpret_cast<uint32_t*>(&Ll);
}

// ---------------- W pre-split: fw fp32 -> g_wb bf16 [o][hi|lo] ----------------
__global__ void __launch_bounds__(256) wconv_kernel(const float* __restrict__ Wt) {
    int idx = blockIdx.x * 256 + threadIdx.x;     // 2048 threads, 4 pairs each
    uint32_t* out = reinterpret_cast<uint32_t*>(g_wb);
#pragma unroll
    for (int i = 0; i < 4; i++) {
        int e = idx + i * 2048;                   // 0..8191
        int o = e >> 6, cp = e & 63;
        float2 w2 = *reinterpret_cast<const float2*>(Wt + o * 128 + 2 * cp);
        uint32_t H, L;
        split2(w2.x, w2.y, H, L);
        out[o * 128 + cp]      = H;
        out[o * 128 + 64 + cp] = L;
    }
}

// ---------------- HMMA GEMM: t = relu(bn(W @ X)), K=384 bf16 split -------------
// Block: 256 thr (8 warps), tile M=64 ch (blockIdx.y half) x N=128 px. 2 CTAs/SM.
// sW bf16[64][264] row=o, k-major [hi|lo].  sX bf16[256][136] row=k (hi 0-127, lo 128-255),
// cols = 128 pixels; B via ldmatrix.x4.trans.
#define WSTR 264
#define RSTR 136
#define HMMA_SMEM ((64 * WSTR + 256 * RSTR) * 2)

__global__ void __launch_bounds__(256, 2) hmma_kernel(
    const float* __restrict__ X,
    const float* __restrict__ fg, const float* __restrict__ fb,
    const float* __restrict__ fm, const float* __restrict__ fv)
{
    extern __shared__ __nv_bfloat16 smem[];
    __nv_bfloat16* sW = smem;                       // 64 x 264
    __nv_bfloat16* sX = smem + 64 * WSTR;           // 256 x 136

    const int tid = threadIdx.x;
    const int wid = tid >> 5, lane = tid & 31;
    const int gp0 = blockIdx.x * 128;               // pixel base
    const int m0g = blockIdx.y * 64;                // channel half
    const int b   = gp0 >> 15, hw0 = gp0 & (HWSZ - 1);

    // ---- stage W half: 2048 uint4, straight copy ----
    {
        const uint4* srcW = reinterpret_cast<const uint4*>(g_wb) + (size_t)m0g * 32;
        char* sWb = reinterpret_cast<char*>(sW);
#pragma unroll
        for (int k = 0; k < 8; k++) {
            int idx = tid + 256 * k;                // row=idx>>5 (0..63), c16=idx&31
            int row = idx >> 5, c16 = idx & 31;
            uint4 v = srcW[row * 32 + c16];
            *reinterpret_cast<uint4*>(sWb + (uint32_t)row * (WSTR * 2) + 16u * c16) = v;
        }
    }
    // ---- stage X: fp32 load + hi/lo split, channel-major rows ----
    {
        const float* xb = X + (size_t)b * CH * HWSZ + hw0;
        char* sXb = reinterpret_cast<char*>(sX);
#pragma unroll
        for (int k = 0; k < 16; k++) {
            int idx = tid + 256 * k;                // row=idx>>5 (0..127), f4=idx&31
            int row = idx >> 5, f4 = idx & 31;
            float4 v = *reinterpret_cast<const float4*>(xb + (size_t)row * HWSZ + 4 * f4);
            uint32_t H0, L0, H1, L1;
            split2(v.x, v.y, H0, L0);
            split2(v.z, v.w, H1, L1);
            *reinterpret_cast<uint2*>(sXb + (uint32_t)row * (RSTR * 2) + 8u * f4)
                = make_uint2(H0, H1);
            *reinterpret_cast<uint2*>(sXb + (uint32_t)(row + 128) * (RSTR * 2) + 8u * f4)
                = make_uint2(L0, L1);
        }
    }
    __syncthreads();

    // ---- warp tile: m = mrow0..+31 (of 64), n = ncol0..+31 (of 128) ----
    const int mrow0 = (wid & 1) * 32;
    const int ncol0 = (wid >> 1) * 32;
    const int r8 = lane & 7, tq = lane >> 3;

    const uint32_t sW0 = smem_u32(sW), sX0 = smem_u32(sX);
    uint32_t aBase[2], bBase[2];
#pragma unroll
    for (int mi = 0; mi < 2; mi++) {
        int row = mrow0 + mi * 16 + (tq & 1) * 8 + r8;
        aBase[mi] = sW0 + (uint32_t)row * (WSTR * 2) + (uint32_t)(tq >> 1) * 16;
    }
    {
        // trans B: lane groups -> (k0-7,n0),(k8-15,n0),(k0-7,n8),(k8-15,n8)
        uint32_t rowlane = (uint32_t)((tq & 1) * 8 + r8);
#pragma unroll
        for (int nj = 0; nj < 2; nj++) {
            uint32_t nbyte = (uint32_t)(ncol0 + nj * 16 + (tq >> 1) * 8) * 2u;
            bBase[nj] = sX0 + rowlane * (RSTR * 2) + nbyte;
        }
    }

    float d[2][4][4];
#pragma unroll
    for (int mi = 0; mi < 2; mi++)
#pragma unroll
        for (int nf = 0; nf < 4; nf++)
#pragma unroll
            for (int q = 0; q < 4; q++) d[mi][nf][q] = 0.f;

    // virtual K: s=0..7 Whi*Xhi, 8..15 Whi*Xlo, 16..23 Wlo*Xhi
#pragma unroll
    for (int s = 0; s < 24; s++) {
        const uint32_t akb = (s < 16) ? ((uint32_t)(s & 7) * 32u) : (256u + (uint32_t)(s & 7) * 32u);
        const uint32_t kbase = (s < 8) ? (uint32_t)(s * 16)
                              : ((s < 16) ? (uint32_t)(128 + (s & 7) * 16)
                                          : (uint32_t)((s & 7) * 16));
        const uint32_t kb = kbase * (RSTR * 2);

        uint32_t a[2][4];
#pragma unroll
        for (int mi = 0; mi < 2; mi++)
            ldm_x4(a[mi][0], a[mi][1], a[mi][2], a[mi][3], aBase[mi] + akb);

        uint32_t bfr[4][2];
#pragma unroll
        for (int nj = 0; nj < 2; nj++) {
            uint32_t r0, r1, r2, r3;
            ldm_x4_t(r0, r1, r2, r3, bBase[nj] + kb);
            bfr[2 * nj][0]     = r0; bfr[2 * nj][1]     = r1;   // n group nj*16 .. +7
            bfr[2 * nj + 1][0] = r2; bfr[2 * nj + 1][1] = r3;   // n group nj*16+8 .. +15
        }
#pragma unroll
        for (int mi = 0; mi < 2; mi++)
#pragma unroll
            for (int nf = 0; nf < 4; nf++)
                mma_bf16(d[mi][nf], a[mi][0], a[mi][1], a[mi][2], a[mi][3],
                         bfr[nf][0], bfr[nf][1]);
    }

    // ---- epilogue: BN + ReLU, store to g_t [p][o] ----
    float fa[2][2], fsh[2][2];
#pragma unroll
    for (int mi = 0; mi < 2; mi++)
#pragma unroll
        for (int hh = 0; hh < 2; hh++) {
            int m = m0g + mrow0 + mi * 16 + hh * 8 + (lane >> 2);
            float aa = fg[m] * rsqrtf(fv[m] + EPSF);
            fa[mi][hh] = aa;
            fsh[mi][hh] = fb[m] - fm[m] * aa;
        }
    float* tb = g_t + (size_t)gp0 * CH + m0g;
#pragma unroll
    for (int mi = 0; mi < 2; mi++) {
        int m0 = mrow0 + mi * 16 + (lane >> 2);
#pragma unroll
        for (int nf = 0; nf < 4; nf++) {
            int n0 = ncol0 + nf * 8 + (lane & 3) * 2;
            tb[(size_t)n0 * CH + m0]           = fmaxf(fmaf(fa[mi][0], d[mi][nf][0], fsh[mi][0]), 0.f);
            tb[(size_t)(n0 + 1) * CH + m0]     = fmaxf(fmaf(fa[mi][0], d[mi][nf][1], fsh[mi][0]), 0.f);
            tb[(size_t)n0 * CH + m0 + 8]       = fmaxf(fmaf(fa[mi][1], d[mi][nf][2], fsh[mi][1]), 0.f);
            tb[(size_t)(n0 + 1) * CH + m0 + 8] = fmaxf(fmaf(fa[mi][1], d[mi][nf][3], fsh[mi][1]), 0.f);
        }
    }
}

// ---------------- kernel 2: sliding-window pos + neighbor max + e2c + cart_out ----
__global__ void __launch_bounds__(128, 4) fuse_kernel(
    const float* __restrict__ cart,
    const unsigned int* __restrict__ mask,
    float* __restrict__ out,
    const float* __restrict__ pw,
    const float* __restrict__ pg, const float* __restrict__ pb,
    const float* __restrict__ pm, const float* __restrict__ pv,
    const float* __restrict__ ew,
    const float* __restrict__ eg, const float* __restrict__ eb,
    const float* __restrict__ em, const float* __restrict__ ev)
{
    __shared__ float s_mu[3][68];
    __shared__ float s_c[3][3][68];
    __shared__ __align__(16) float s_geo[64 * 132];
    __shared__ float s_ews[3 * CH];
    __shared__ float s_esh[3];

    const int tid = threadIdx.x;
    const int w0  = blockIdx.x * 64;
    const int h   = blockIdx.y;
    const int b   = blockIdx.z;
    const int cb  = b * 3 * HWSZ;

    for (int e = tid; e < 198; e += 128) {
        int r = e / 66, col = e - r * 66;
        int hh = h - 1 + r, ww = w0 - 1 + col;
        float mu = 0.f, c0 = 0.f, c1 = 0.f, c2 = 0.f;
        if ((unsigned)hh < HD && (unsigned)ww < WD) {
            int p = hh * WD + ww;
            mu = (mask[b * HWSZ + p] != 0u) ? 1.f : 0.f;
            c0 = cart[cb + p];
            c1 = cart[cb + HWSZ + p];
            c2 = cart[cb + 2 * HWSZ + p];
        }
        s_mu[r][col] = mu;
        s_c[0][r][col] = c0; s_c[1][r][col] = c1; s_c[2][r][col] = c2;
    }
    {
        float ea0 = eg[0] * rsqrtf(ev[0] + EPSF);
        float ea1 = eg[1] * rsqrtf(ev[1] + EPSF);
        float ea2 = eg[2] * rsqrtf(ev[2] + EPSF);
        s_ews[tid]       = ea0 * ew[tid];
        s_ews[128 + tid] = ea1 * ew[128 + tid];
        s_ews[256 + tid] = ea2 * ew[256 + tid];
        if (tid < 3) {
            float ea = eg[tid] * rsqrtf(ev[tid] + EPSF);
            s_esh[tid] = eb[tid] - em[tid] * ea;
        }
    }

    const int wa = tid >> 5;
    const int l  = tid & 31;
    const int o0 = 4 * l;
    float A0[4], A1[4], A2[4], B2[4];
#pragma unroll
    for (int k = 0; k < 4; k++) {
        int o = o0 + k;
        float pa = pg[o] * rsqrtf(pv[o] + EPSF);
        A0[k] = pa * pw[o * 3];
        A1[k] = pa * pw[o * 3 + 1];
        A2[k] = pa * pw[o * 3 + 2];
        B2[k] = pb[o] - pm[o] * pa;
    }
    __syncthreads();

    const int base = wa * 16;
    int rowoff[3];
#pragma unroll
    for (int r = 0; r < 3; r++) {
        int hh = h - 1 + r;
        hh = hh < 0 ? 0 : (hh > HD - 1 ? HD - 1 : hh);
        rowoff[r] = hh * WD;
    }
    const float* tbase = g_t + (size_t)b * HWSZ * CH + o0;

    float tw[3][3][4];
    float vw[3][3][4];

#pragma unroll
    for (int ci = 0; ci < 3; ci++) {
        int lc = base + ci;
        int colg = w0 - 1 + lc;
        colg = colg < 0 ? 0 : (colg > WD - 1 ? WD - 1 : colg);
#pragma unroll
        for (int r = 0; r < 3; r++) {
            float4 tv = *reinterpret_cast<const float4*>(tbase + (size_t)(rowoff[r] + colg) * CH);
            tw[r][ci][0] = tv.x; tw[r][ci][1] = tv.y; tw[r][ci][2] = tv.z; tw[r][ci][3] = tv.w;
            float c0 = s_c[0][r][lc], c1 = s_c[1][r][lc], c2 = s_c[2][r][lc];
#pragma unroll
            for (int k = 0; k < 4; k++)
                vw[r][ci][k] = fmaf(A0[k], c0, fmaf(A1[k], c1, A2[k] * c2));
        }
    }

#pragma unroll
    for (int j = 0; j < 16; j++) {
        float tn[3][4];
        const int lcn = base + j + 3;
        if (j < 15) {
            int colg = w0 - 1 + lcn;
            colg = colg > WD - 1 ? WD - 1 : colg;
#pragma unroll
            for (int r = 0; r < 3; r++) {
                float4 tv = *reinterpret_cast<const float4*>(tbase + (size_t)(rowoff[r] + colg) * CH);
                tn[r][0] = tv.x; tn[r][1] = tv.y; tn[r][2] = tv.z; tn[r][3] = tv.w;
            }
        }

        float wc[4], mx[4];
#pragma unroll
        for (int k = 0; k < 4; k++) { wc[k] = B2[k] - vw[1][1][k]; mx[k] = 0.f; }
#pragma unroll
        for (int r = 0; r < 3; r++)
#pragma unroll
            for (int ci = 0; ci < 3; ci++) {
                float mu = s_mu[r][base + j + ci];
#pragma unroll
                for (int k = 0; k < 4; k++) {
                    float pos = fmaxf(vw[r][ci][k] + wc[k], 0.0f);
                    mx[k] = fmaxf(mx[k], (tw[r][ci][k] + pos) * mu);
                }
            }
        *reinterpret_cast<float4*>(&s_geo[(base + j) * 132 + o0]) =
            make_float4(mx[0], mx[1], mx[2], mx[3]);

        if (j < 15) {
#pragma unroll
            for (int r = 0; r < 3; r++) {
#pragma unroll
                for (int k = 0; k < 4; k++) {
                    tw[r][0][k] = tw[r][1][k]; tw[r][1][k] = tw[r][2][k]; tw[r][2][k] = tn[r][k];
                    vw[r][0][k] = vw[r][1][k]; vw[r][1][k] = vw[r][2][k];
                }
                float c0 = s_c[0][r][lcn], c1 = s_c[1][r][lcn], c2 = s_c[2][r][lcn];
#pragma unroll
                for (int k = 0; k < 4; k++)
                    vw[r][2][k] = fmaf(A0[k], c0, fmaf(A1[k], c1, A2[k] * c2));
            }
        }
    }
    __syncthreads();

    if (tid < 64) {
        int pl = tid;
        float s0 = 0.f, s1 = 0.f, s2 = 0.f;
#pragma unroll 4
        for (int oo = 0; oo < 128; oo++) {
            float gv = s_geo[pl * 132 + oo];
            s0 = fmaf(s_ews[oo],       gv, s0);
            s1 = fmaf(s_ews[128 + oo], gv, s1);
            s2 = fmaf(s_ews[256 + oo], gv, s2);
        }
        float mc = s_mu[1][pl + 1];
        int hw = h * WD + w0 + pl;
        const size_t OUTC = (size_t)BD * CH * HWSZ;
        out[OUTC + cb + hw]            = cart[cb + hw]            + (s0 + s_esh[0]) * mc;
        out[OUTC + cb + HWSZ + hw]     = cart[cb + HWSZ + hw]     + (s1 + s_esh[1]) * mc;
        out[OUTC + cb + 2 * HWSZ + hw] = cart[cb + 2 * HWSZ + hw] + (s2 + s_esh[2]) * mc;
    }

    const size_t gbase = (size_t)b * CH * HWSZ + (size_t)(h * WD + w0);
    for (int k = 0; k < 64; k++) {
        int idx = tid + k * 128;
        int oo = idx >> 6, pl = idx & 63;
        out[gbase + (size_t)oo * HWSZ + pl] = s_geo[pl * 132 + oo];
    }
}

// ---------------- launch ----------------
extern "C" void kernel_launch(void* const* d_in, const int* in_sizes, int n_in,
                              void* d_out, int out_size)
{
    const float*        features = (const float*)d_in[0];
    const float*        cart     = (const float*)d_in[1];
    const unsigned int* mask     = (const unsigned int*)d_in[2];
    const float* pw = (const float*)d_in[3];
    const float* pg = (const float*)d_in[4];
    const float* pb = (const float*)d_in[5];
    const float* pm = (const float*)d_in[6];
    const float* pv = (const float*)d_in[7];
    const float* fw = (const float*)d_in[8];
    const float* fg = (const float*)d_in[9];
    const float* fb = (const float*)d_in[10];
    const float* fm = (const float*)d_in[11];
    const float* fv = (const float*)d_in[12];
    const float* ew = (const float*)d_in[13];
    const float* eg = (const float*)d_in[14];
    const float* eb = (const float*)d_in[15];
    const float* em = (const float*)d_in[16];
    const float* ev = (const float*)d_in[17];
    float* out = (float*)d_out;

    cudaFuncSetAttribute(hmma_kernel, cudaFuncAttributeMaxDynamicSharedMemorySize, HMMA_SMEM);

    wconv_kernel<<<8, 256>>>(fw);
    hmma_kernel<<<dim3(BD * HWSZ / 128, 2), 256, HMMA_SMEM>>>(features, fg, fb, fm, fv);
    fuse_kernel<<<dim3(WD / 64, HD, BD), 128>>>(cart, mask, out,
                                                pw, pg, pb, pm, pv,
                                                ew, eg, eb, em, ev);
}

// round 17
// speedup vs baseline: 3.3473x; 1.1085x over previous
#include <cuda_runtime.h>
#include <cuda_bf16.h>
#include <cstdint>
#include <cstddef>

#define HWSZ 32768
#define WD   512
#define HD   64
#define BD   2
#define CH   128
#define EPSF 1e-5f
#define MNEG 1e30f

// ---------------- scratch (no runtime allocation allowed) ----------------
__device__ float g_t[(size_t)BD * HWSZ * CH];   // relu(bn(fw@x)), [b*HW+p][o]

__device__ __forceinline__ uint32_t smem_u32(const void* p) {
    uint32_t a;
    asm("{ .reg .u64 t; cvta.to.shared.u64 t, %1; cvt.u32.u64 %0, t; }" : "=r"(a) : "l"(p));
    return a;
}
__device__ __forceinline__ void ldm_x4(uint32_t& r0, uint32_t& r1, uint32_t& r2, uint32_t& r3,
                                       uint32_t addr) {
    asm volatile("ldmatrix.sync.aligned.m8n8.x4.shared.b16 {%0,%1,%2,%3}, [%4];"
        : "=r"(r0), "=r"(r1), "=r"(r2), "=r"(r3) : "r"(addr));
}
__device__ __forceinline__ void ldm_x4_t(uint32_t& r0, uint32_t& r1, uint32_t& r2, uint32_t& r3,
                                         uint32_t addr) {
    asm volatile("ldmatrix.sync.aligned.m8n8.x4.trans.shared.b16 {%0,%1,%2,%3}, [%4];"
        : "=r"(r0), "=r"(r1), "=r"(r2), "=r"(r3) : "r"(addr));
}
__device__ __forceinline__ void mma_bf16(float* d, uint32_t a0, uint32_t a1, uint32_t a2,
                                         uint32_t a3, uint32_t b0, uint32_t b1) {
    asm volatile("mma.sync.aligned.m16n8k16.row.col.f32.bf16.bf16.f32 "
        "{%0,%1,%2,%3}, {%4,%5,%6,%7}, {%8,%9}, {%0,%1,%2,%3};"
        : "+f"(d[0]), "+f"(d[1]), "+f"(d[2]), "+f"(d[3])
        : "r"(a0), "r"(a1), "r"(a2), "r"(a3), "r"(b0), "r"(b1));
}
__device__ __forceinline__ void split2(float x0, float x1, uint32_t& H, uint32_t& L) {
    __nv_bfloat16 h0 = __float2bfloat16(x0), h1 = __float2bfloat16(x1);
    __nv_bfloat16 l0 = __float2bfloat16(x0 - __bfloat162float(h0));
    __nv_bfloat16 l1 = __float2bfloat16(x1 - __bfloat162float(h1));
    __nv_bfloat162 Hh = __halves2bfloat162(h0, h1);
    __nv_bfloat162 Ll = __halves2bfloat162(l0, l1);
    H = *reinterpret_cast<uint32_t*>(&Hh);
    L = *reinterpret_cast<uint32_t*>(&Ll);
}

// ---------------- HMMA GEMM: t = relu(bn(W @ X)), K=384 bf16 split -------------
// Block: 256 thr (8 warps), tile M=64 ch (blockIdx.y half) x N=128 px. 2 CTAs/SM.
// sW bf16[64][264] row=o, k-major [hi|lo] (converted in-block from fw fp32).
// sX bf16[256][136] row=k (hi 0-127, lo 128-255), cols = 128 pixels; B via ldmatrix.trans.
#define WSTR 264
#define RSTR 136
#define HMMA_SMEM ((64 * WSTR + 256 * RSTR) * 2)

__global__ void __launch_bounds__(256, 2) hmma_kernel(
    const float* __restrict__ X,  const float* __restrict__ Wt,
    const float* __restrict__ fg, const float* __restrict__ fb,
    const float* __restrict__ fm, const float* __restrict__ fv)
{
    extern __shared__ __nv_bfloat16 smem[];
    __nv_bfloat16* sW = smem;                       // 64 x 264
    __nv_bfloat16* sX = smem + 64 * WSTR;           // 256 x 136

    const int tid = threadIdx.x;
    const int wid = tid >> 5, lane = tid & 31;
    const int gp0 = blockIdx.x * 128;               // pixel base
    const int m0g = blockIdx.y * 64;                // channel half
    const int b   = gp0 >> 15, hw0 = gp0 & (HWSZ - 1);

    // ---- stage W half: convert fp32 -> bf16 hi/lo in-block (L2-hot source) ----
    {
        const float* wsrc = Wt + (size_t)m0g * 128;
        char* sWb = reinterpret_cast<char*>(sW);
#pragma unroll
        for (int k = 0; k < 16; k++) {
            int idx = tid + 256 * k;                // 4096 pairs: row=idx>>6, cp=idx&63
            int row = idx >> 6, cp = idx & 63;
            float2 w2 = *reinterpret_cast<const float2*>(wsrc + row * 128 + 2 * cp);
            uint32_t H, L;
            split2(w2.x, w2.y, H, L);
            *reinterpret_cast<uint32_t*>(sWb + (uint32_t)row * (WSTR * 2) + 4u * cp)        = H;
            *reinterpret_cast<uint32_t*>(sWb + (uint32_t)row * (WSTR * 2) + 256u + 4u * cp) = L;
        }
    }
    // ---- stage X: fp32 load + hi/lo split, channel-major rows ----
    {
        const float* xb = X + (size_t)b * CH * HWSZ + hw0;
        char* sXb = reinterpret_cast<char*>(sX);
#pragma unroll
        for (int k = 0; k < 16; k++) {
            int idx = tid + 256 * k;                // row=idx>>5 (0..127), f4=idx&31
            int row = idx >> 5, f4 = idx & 31;
            float4 v = *reinterpret_cast<const float4*>(xb + (size_t)row * HWSZ + 4 * f4);
            uint32_t H0, L0, H1, L1;
            split2(v.x, v.y, H0, L0);
            split2(v.z, v.w, H1, L1);
            *reinterpret_cast<uint2*>(sXb + (uint32_t)row * (RSTR * 2) + 8u * f4)
                = make_uint2(H0, H1);
            *reinterpret_cast<uint2*>(sXb + (uint32_t)(row + 128) * (RSTR * 2) + 8u * f4)
                = make_uint2(L0, L1);
        }
    }
    __syncthreads();

    // ---- warp tile: m = mrow0..+31 (of 64), n = ncol0..+31 (of 128) ----
    const int mrow0 = (wid & 1) * 32;
    const int ncol0 = (wid >> 1) * 32;
    const int r8 = lane & 7, tq = lane >> 3;

    const uint32_t sW0 = smem_u32(sW), sX0 = smem_u32(sX);
    uint32_t aBase[2], bBase[2];
#pragma unroll
    for (int mi = 0; mi < 2; mi++) {
        int row = mrow0 + mi * 16 + (tq & 1) * 8 + r8;
        aBase[mi] = sW0 + (uint32_t)row * (WSTR * 2) + (uint32_t)(tq >> 1) * 16;
    }
    {
        uint32_t rowlane = (uint32_t)((tq & 1) * 8 + r8);
#pragma unroll
        for (int nj = 0; nj < 2; nj++) {
            uint32_t nbyte = (uint32_t)(ncol0 + nj * 16 + (tq >> 1) * 8) * 2u;
            bBase[nj] = sX0 + rowlane * (RSTR * 2) + nbyte;
        }
    }

    float d[2][4][4];
#pragma unroll
    for (int mi = 0; mi < 2; mi++)
#pragma unroll
        for (int nf = 0; nf < 4; nf++)
#pragma unroll
            for (int q = 0; q < 4; q++) d[mi][nf][q] = 0.f;

    // virtual K: s=0..7 Whi*Xhi, 8..15 Whi*Xlo, 16..23 Wlo*Xhi
#pragma unroll
    for (int s = 0; s < 24; s++) {
        const uint32_t akb = (s < 16) ? ((uint32_t)(s & 7) * 32u) : (256u + (uint32_t)(s & 7) * 32u);
        const uint32_t kbase = (s < 8) ? (uint32_t)(s * 16)
                              : ((s < 16) ? (uint32_t)(128 + (s & 7) * 16)
                                          : (uint32_t)((s & 7) * 16));
        const uint32_t kb = kbase * (RSTR * 2);

        uint32_t a[2][4];
#pragma unroll
        for (int mi = 0; mi < 2; mi++)
            ldm_x4(a[mi][0], a[mi][1], a[mi][2], a[mi][3], aBase[mi] + akb);

        uint32_t bfr[4][2];
#pragma unroll
        for (int nj = 0; nj < 2; nj++) {
            uint32_t r0, r1, r2, r3;
            ldm_x4_t(r0, r1, r2, r3, bBase[nj] + kb);
            bfr[2 * nj][0]     = r0; bfr[2 * nj][1]     = r1;
            bfr[2 * nj + 1][0] = r2; bfr[2 * nj + 1][1] = r3;
        }
#pragma unroll
        for (int mi = 0; mi < 2; mi++)
#pragma unroll
            for (int nf = 0; nf < 4; nf++)
                mma_bf16(d[mi][nf], a[mi][0], a[mi][1], a[mi][2], a[mi][3],
                         bfr[nf][0], bfr[nf][1]);
    }

    // ---- epilogue: BN + ReLU, store to g_t [p][o] ----
    float fa[2][2], fsh[2][2];
#pragma unroll
    for (int mi = 0; mi < 2; mi++)
#pragma unroll
        for (int hh = 0; hh < 2; hh++) {
            int m = m0g + mrow0 + mi * 16 + hh * 8 + (lane >> 2);
            float aa = fg[m] * rsqrtf(fv[m] + EPSF);
            fa[mi][hh] = aa;
            fsh[mi][hh] = fb[m] - fm[m] * aa;
        }
    float* tb = g_t + (size_t)gp0 * CH + m0g;
#pragma unroll
    for (int mi = 0; mi < 2; mi++) {
        int m0 = mrow0 + mi * 16 + (lane >> 2);
#pragma unroll
        for (int nf = 0; nf < 4; nf++) {
            int n0 = ncol0 + nf * 8 + (lane & 3) * 2;
            tb[(size_t)n0 * CH + m0]           = fmaxf(fmaf(fa[mi][0], d[mi][nf][0], fsh[mi][0]), 0.f);
            tb[(size_t)(n0 + 1) * CH + m0]     = fmaxf(fmaf(fa[mi][0], d[mi][nf][1], fsh[mi][0]), 0.f);
            tb[(size_t)n0 * CH + m0 + 8]       = fmaxf(fmaf(fa[mi][1], d[mi][nf][2], fsh[mi][1]), 0.f);
            tb[(size_t)(n0 + 1) * CH + m0 + 8] = fmaxf(fmaf(fa[mi][1], d[mi][nf][3], fsh[mi][1]), 0.f);
        }
    }
}

// ---------------- kernel 2: sliding-window pos + neighbor max + e2c + cart_out ----
// Mask folded additively: m in {0, -1e30}; per cell keep tm = t+m, vtm = v+t+m.
// cand = max(vtm + wc, tm) == (t + relu(v - vc + b2)) or ~-1e30 if masked.
__global__ void __launch_bounds__(128, 4) fuse_kernel(
    const float* __restrict__ cart,
    const unsigned int* __restrict__ mask,
    float* __restrict__ out,
    const float* __restrict__ pw,
    const float* __restrict__ pg, const float* __restrict__ pb,
    const float* __restrict__ pm, const float* __restrict__ pv,
    const float* __restrict__ ew,
    const float* __restrict__ eg, const float* __restrict__ eb,
    const float* __restrict__ em, const float* __restrict__ ev)
{
    __shared__ float s_mu[3][68];
    __shared__ float s_c[3][3][68];
    __shared__ __align__(16) float s_geo[64 * 132];
    __shared__ float s_ews[3 * CH];
    __shared__ float s_esh[3];

    const int tid = threadIdx.x;
    const int w0  = blockIdx.x * 64;
    const int h   = blockIdx.y;
    const int b   = blockIdx.z;
    const int cb  = b * 3 * HWSZ;

    for (int e = tid; e < 198; e += 128) {
        int r = e / 66, col = e - r * 66;
        int hh = h - 1 + r, ww = w0 - 1 + col;
        float mu = 0.f, c0 = 0.f, c1 = 0.f, c2 = 0.f;
        if ((unsigned)hh < HD && (unsigned)ww < WD) {
            int p = hh * WD + ww;
            mu = (mask[b * HWSZ + p] != 0u) ? 1.f : 0.f;
            c0 = cart[cb + p];
            c1 = cart[cb + HWSZ + p];
            c2 = cart[cb + 2 * HWSZ + p];
        }
        s_mu[r][col] = mu;
        s_c[0][r][col] = c0; s_c[1][r][col] = c1; s_c[2][r][col] = c2;
    }
    {
        float ea0 = eg[0] * rsqrtf(ev[0] + EPSF);
        float ea1 = eg[1] * rsqrtf(ev[1] + EPSF);
        float ea2 = eg[2] * rsqrtf(ev[2] + EPSF);
        s_ews[tid]       = ea0 * ew[tid];
        s_ews[128 + tid] = ea1 * ew[128 + tid];
        s_ews[256 + tid] = ea2 * ew[256 + tid];
        if (tid < 3) {
            float ea = eg[tid] * rsqrtf(ev[tid] + EPSF);
            s_esh[tid] = eb[tid] - em[tid] * ea;
        }
    }

    const int wa = tid >> 5;
    const int l  = tid & 31;
    const int o0 = 4 * l;
    float A0[4], A1[4], A2[4], B2[4];
#pragma unroll
    for (int k = 0; k < 4; k++) {
        int o = o0 + k;
        float pa = pg[o] * rsqrtf(pv[o] + EPSF);
        A0[k] = pa * pw[o * 3];
        A1[k] = pa * pw[o * 3 + 1];
        A2[k] = pa * pw[o * 3 + 2];
        B2[k] = pb[o] - pm[o] * pa;
    }
    __syncthreads();

    const int base = wa * 16;
    int rowoff[3];
#pragma unroll
    for (int r = 0; r < 3; r++) {
        int hh = h - 1 + r;
        hh = hh < 0 ? 0 : (hh > HD - 1 ? HD - 1 : hh);
        rowoff[r] = hh * WD;
    }
    const float* tbase = g_t + (size_t)b * HWSZ * CH + o0;

    float tm[3][3][4];    // t + m
    float vtm[3][3][4];   // v + t + m

#pragma unroll
    for (int ci = 0; ci < 3; ci++) {
        int lc = base + ci;
        int colg = w0 - 1 + lc;
        colg = colg < 0 ? 0 : (colg > WD - 1 ? WD - 1 : colg);
#pragma unroll
        for (int r = 0; r < 3; r++) {
            float4 tv = *reinterpret_cast<const float4*>(tbase + (size_t)(rowoff[r] + colg) * CH);
            float tt[4] = {tv.x, tv.y, tv.z, tv.w};
            float mu = s_mu[r][lc];
            float mb = (mu - 1.f) * MNEG;          // 0 or -1e30
            float c0 = s_c[0][r][lc], c1 = s_c[1][r][lc], c2 = s_c[2][r][lc];
#pragma unroll
            for (int k = 0; k < 4; k++) {
                float v = fmaf(A0[k], c0, fmaf(A1[k], c1, A2[k] * c2));
                tm[r][ci][k]  = tt[k] + mb;
                vtm[r][ci][k] = v + tt[k] + mb;
            }
        }
    }

#pragma unroll
    for (int j = 0; j < 16; j++) {
        float tn[3][4];
        const int lcn = base + j + 3;
        if (j < 15) {
            int colg = w0 - 1 + lcn;
            colg = colg > WD - 1 ? WD - 1 : colg;
#pragma unroll
            for (int r = 0; r < 3; r++) {
                float4 tv = *reinterpret_cast<const float4*>(tbase + (size_t)(rowoff[r] + colg) * CH);
                tn[r][0] = tv.x; tn[r][1] = tv.y; tn[r][2] = tv.z; tn[r][3] = tv.w;
            }
        }

        // wc[k] = B2[k] - v_center (recomputed from s_c; center = row 1, col base+j+1)
        float wc[4], mx[4];
        {
            const int lcc = base + j + 1;
            float c0 = s_c[0][1][lcc], c1 = s_c[1][1][lcc], c2 = s_c[2][1][lcc];
#pragma unroll
            for (int k = 0; k < 4; k++) {
                wc[k] = fmaf(-A0[k], c0, fmaf(-A1[k], c1, fmaf(-A2[k], c2, B2[k])));
                mx[k] = 0.f;
            }
        }
#pragma unroll
        for (int r = 0; r < 3; r++)
#pragma unroll
            for (int ci = 0; ci < 3; ci++)
#pragma unroll
                for (int k = 0; k < 4; k++) {
                    float cand = fmaxf(vtm[r][ci][k] + wc[k], tm[r][ci][k]);
                    mx[k] = fmaxf(mx[k], cand);
                }
        *reinterpret_cast<float4*>(&s_geo[(base + j) * 132 + o0]) =
            make_float4(mx[0], mx[1], mx[2], mx[3]);

        if (j < 15) {
#pragma unroll
            for (int r = 0; r < 3; r++) {
                float mu = s_mu[r][lcn];
                float mb = (mu - 1.f) * MNEG;
                float c0 = s_c[0][r][lcn], c1 = s_c[1][r][lcn], c2 = s_c[2][r][lcn];
#pragma unroll
                for (int k = 0; k < 4; k++) {
                    tm[r][0][k]  = tm[r][1][k];  tm[r][1][k]  = tm[r][2][k];
                    vtm[r][0][k] = vtm[r][1][k]; vtm[r][1][k] = vtm[r][2][k];
                    float v = fmaf(A0[k], c0, fmaf(A1[k], c1, A2[k] * c2));
                    tm[r][2][k]  = tn[r][k] + mb;
                    vtm[r][2][k] = v + tn[r][k] + mb;
                }
            }
        }
    }
    __syncthreads();

    if (tid < 64) {
        int pl = tid;
        float s0 = 0.f, s1 = 0.f, s2 = 0.f;
#pragma unroll 4
        for (int oo = 0; oo < 128; oo++) {
            float gv = s_geo[pl * 132 + oo];
            s0 = fmaf(s_ews[oo],       gv, s0);
            s1 = fmaf(s_ews[128 + oo], gv, s1);
            s2 = fmaf(s_ews[256 + oo], gv, s2);
        }
        float mc = s_mu[1][pl + 1];
        int hw = h * WD + w0 + pl;
        const size_t OUTC = (size_t)BD * CH * HWSZ;
        out[OUTC + cb + hw]            = cart[cb + hw]            + (s0 + s_esh[0]) * mc;
        out[OUTC + cb + HWSZ + hw]     = cart[cb + HWSZ + hw]     + (s1 + s_esh[1]) * mc;
        out[OUTC + cb + 2 * HWSZ + hw] = cart[cb + 2 * HWSZ + hw] + (s2 + s_esh[2]) * mc;
    }

    const size_t gbase = (size_t)b * CH * HWSZ + (size_t)(h * WD + w0);
    for (int k = 0; k < 64; k++) {
        int idx = tid + k * 128;
        int oo = idx >> 6, pl = idx & 63;
        out[gbase + (size_t)oo * HWSZ + pl] = s_geo[pl * 132 + oo];
    }
}

// ---------------- launch ----------------
extern "C" void kernel_launch(void* const* d_in, const int* in_sizes, int n_in,
                              void* d_out, int out_size)
{
    const float*        features = (const float*)d_in[0];
    const float*        cart     = (const float*)d_in[1];
    const unsigned int* mask     = (const unsigned int*)d_in[2];
    const float* pw = (const float*)d_in[3];
    const float* pg = (const float*)d_in[4];
    const float* pb = (const float*)d_in[5];
    const float* pm = (const float*)d_in[6];
    const float* pv = (const float*)d_in[7];
    const float* fw = (const float*)d_in[8];
    const float* fg = (const float*)d_in[9];
    const float* fb = (const float*)d_in[10];
    const float* fm = (const float*)d_in[11];
    const float* fv = (const float*)d_in[12];
    const float* ew = (const float*)d_in[13];
    const float* eg = (const float*)d_in[14];
    const float* eb = (const float*)d_in[15];
    const float* em = (const float*)d_in[16];
    const float* ev = (const float*)d_in[17];
    float* out = (float*)d_out;

    cudaFuncSetAttribute(hmma_kernel, cudaFuncAttributeMaxDynamicSharedMemorySize, HMMA_SMEM);

    hmma_kernel<<<dim3(BD * HWSZ / 128, 2), 256, HMMA_SMEM>>>(features, fw, fg, fb, fm, fv);
    fuse_kernel<<<dim3(WD / 64, HD, BD), 128>>>(cart, mask, out,
                                                pw, pg, pb, pm, pv,
                                                ew, eg, eb, em, ev);
}